// round 1
// baseline (speedup 1.0000x reference)
#include <cuda_runtime.h>

// VectorQuantizer fused kernel set.
// inputs:  d_in[0] = inputs  [16,32,32,256] f32  (N=16384 rows, D=256)
//          d_in[1] = codebook [4096,256] f32     (K=4096)
// output:  d_out[0 .. N*D)   = embeddings (straight-through value)
//          d_out[N*D]        = scalar loss

#define N_ROWS 16384
#define DIM    256
#define KCB    4096
#define BM     128
#define BN     128
#define BK     16

// ---------------- scratch (__device__ globals; no allocation allowed) -------
__device__ unsigned long long g_row_argmin[N_ROWS];  // (enc(dist)<<32)|col
__device__ unsigned int       g_class_min[KCB];      // enc(min dist per class)
__device__ int                g_active[KCB];
__device__ float              g_mse;
__device__ float              g_xsq[N_ROWS];
__device__ float              g_csq[KCB];

// monotonic float <-> uint encoding (order-preserving incl. negatives)
__device__ __forceinline__ unsigned int enc_f(float f) {
    unsigned int u = __float_as_uint(f);
    return (u & 0x80000000u) ? ~u : (u | 0x80000000u);
}
__device__ __forceinline__ float dec_f(unsigned int e) {
    return (e & 0x80000000u) ? __uint_as_float(e ^ 0x80000000u)
                             : __uint_as_float(~e);
}

// ---------------- init --------------------------------------------------------
__global__ void vq_init_kernel() {
    int i = blockIdx.x * blockDim.x + threadIdx.x;
    if (i < N_ROWS) g_row_argmin[i] = 0xFFFFFFFFFFFFFFFFull;
    if (i < KCB) { g_class_min[i] = 0xFFFFFFFFu; g_active[i] = 0; }
    if (i == 0) g_mse = 0.0f;
}

// ---------------- row squared norms (inputs and codebook) --------------------
// one warp per row, vectorized float4 loads
__global__ void vq_sqsum_kernel(const float* __restrict__ x, int rows, int is_codebook) {
    int warp = threadIdx.x >> 5;
    int lane = threadIdx.x & 31;
    int row  = blockIdx.x * (blockDim.x >> 5) + warp;
    if (row >= rows) return;
    const float4* p = reinterpret_cast<const float4*>(x + (size_t)row * DIM);
    float s = 0.0f;
#pragma unroll
    for (int j = lane; j < DIM / 4; j += 32) {
        float4 v = p[j];
        s += v.x * v.x + v.y * v.y + v.z * v.z + v.w * v.w;
    }
#pragma unroll
    for (int o = 16; o; o >>= 1) s += __shfl_xor_sync(0xFFFFFFFFu, s, o);
    if (lane == 0) {
        if (is_codebook) g_csq[row] = s; else g_xsq[row] = s;
    }
}

// ---------------- fused distance GEMM + argmin + per-class min ----------------
// 128x128 output tile, BK=16 k-slice, 256 threads, 8x8 per-thread microtile.
__global__ __launch_bounds__(256, 2)
void vq_gemm_kernel(const float* __restrict__ A,   // inputs  [N_ROWS, DIM]
                    const float* __restrict__ B) { // codebook [KCB, DIM]
    __shared__ float As[BK][BM];
    __shared__ float Bs[BK][BN];
    __shared__ unsigned int scls[BN];

    const int bx = blockIdx.x;   // class-tile
    const int by = blockIdx.y;   // row-tile
    const int tid = threadIdx.x;
    const int tx = tid & 15;     // 16 cols of threads
    const int ty = tid >> 4;     // 16 rows of threads

    if (tid < BN) scls[tid] = 0xFFFFFFFFu;

    float acc[8][8];
#pragma unroll
    for (int i = 0; i < 8; i++)
#pragma unroll
        for (int j = 0; j < 8; j++) acc[i][j] = 0.0f;

    const float* Ab = A + (size_t)by * BM * DIM;
    const float* Bb = B + (size_t)bx * BN * DIM;

    for (int k0 = 0; k0 < DIM; k0 += BK) {
        // load 128x16 of A and B (512 float4 each; 2 per thread)
#pragma unroll
        for (int l = 0; l < 2; l++) {
            int f   = tid + l * 256;
            int row = f >> 2;
            int c4  = (f & 3) << 2;
            float4 va = *reinterpret_cast<const float4*>(Ab + (size_t)row * DIM + k0 + c4);
            As[c4 + 0][row] = va.x; As[c4 + 1][row] = va.y;
            As[c4 + 2][row] = va.z; As[c4 + 3][row] = va.w;
            float4 vb = *reinterpret_cast<const float4*>(Bb + (size_t)row * DIM + k0 + c4);
            Bs[c4 + 0][row] = vb.x; Bs[c4 + 1][row] = vb.y;
            Bs[c4 + 2][row] = vb.z; Bs[c4 + 3][row] = vb.w;
        }
        __syncthreads();
#pragma unroll
        for (int d = 0; d < BK; d++) {
            float ra[8], rb[8];
#pragma unroll
            for (int i = 0; i < 8; i++) ra[i] = As[d][ty * 8 + i];
#pragma unroll
            for (int j = 0; j < 8; j++) rb[j] = Bs[d][tx * 8 + j];
#pragma unroll
            for (int i = 0; i < 8; i++)
#pragma unroll
                for (int j = 0; j < 8; j++) acc[i][j] = fmaf(ra[i], rb[j], acc[i][j]);
        }
        __syncthreads();
    }

    // ---- epilogue: distances = (xsq + csq) - 2*cross ----
    const int rowBase = by * BM + ty * 8;
    const int colBase = bx * BN + tx * 8;

    float csq[8], xsq[8];
#pragma unroll
    for (int j = 0; j < 8; j++) csq[j] = g_csq[colBase + j];
#pragma unroll
    for (int i = 0; i < 8; i++) xsq[i] = g_xsq[rowBase + i];

    unsigned int cmin[8];
#pragma unroll
    for (int j = 0; j < 8; j++) cmin[j] = 0xFFFFFFFFu;

#pragma unroll
    for (int i = 0; i < 8; i++) {
        unsigned long long best = 0xFFFFFFFFFFFFFFFFull;
#pragma unroll
        for (int j = 0; j < 8; j++) {
            float d = (xsq[i] + csq[j]) - 2.0f * acc[i][j];
            unsigned int e = enc_f(d);
            unsigned long long pk =
                ((unsigned long long)e << 32) | (unsigned int)(colBase + j);
            if (pk < best) best = pk;
            if (e < cmin[j]) cmin[j] = e;
        }
        // reduce across the 16 tx-lanes (contiguous half-warp groups)
#pragma unroll
        for (int o = 8; o; o >>= 1) {
            unsigned long long other = __shfl_xor_sync(0xFFFFFFFFu, best, o);
            if (other < best) best = other;
        }
        if (tx == 0) atomicMin(&g_row_argmin[rowBase + i], best);
    }

    // per-class min (full distance) into shared, then one global atomic per class
#pragma unroll
    for (int j = 0; j < 8; j++) atomicMin(&scls[tx * 8 + j], cmin[j]);
    __syncthreads();
    if (tid < BN) atomicMin(&g_class_min[bx * BN + tid], scls[tid]);
}

// ---------------- gather + MSE + active flags --------------------------------
__global__ void vq_gather_kernel(const float* __restrict__ x,
                                 const float* __restrict__ cb,
                                 float* __restrict__ out) {
    int warp = threadIdx.x >> 5;
    int lane = threadIdx.x & 31;
    int row  = blockIdx.x * 8 + warp;
    float s = 0.0f;
    if (row < N_ROWS) {
        unsigned int tok = (unsigned int)(g_row_argmin[row] & 0xFFFFFFFFull);
        if (lane == 0) g_active[tok] = 1;
        const float4* cp = reinterpret_cast<const float4*>(cb + (size_t)tok * DIM);
        const float4* xp = reinterpret_cast<const float4*>(x + (size_t)row * DIM);
        float4*       op = reinterpret_cast<float4*>(out + (size_t)row * DIM);
#pragma unroll
        for (int j = lane; j < DIM / 4; j += 32) {
            float4 c = cp[j];
            float4 v = xp[j];
            op[j] = c;
            float dx = c.x - v.x, dy = c.y - v.y, dz = c.z - v.z, dw = c.w - v.w;
            s += dx * dx + dy * dy + dz * dz + dw * dw;
        }
    }
#pragma unroll
    for (int o = 16; o; o >>= 1) s += __shfl_xor_sync(0xFFFFFFFFu, s, o);
    __shared__ float ws[8];
    if (lane == 0) ws[warp] = s;
    __syncthreads();
    if (threadIdx.x == 0) {
        float t = 0.0f;
#pragma unroll
        for (int w = 0; w < 8; w++) t += ws[w];
        atomicAdd(&g_mse, t);
    }
}

// ---------------- finalize loss ----------------------------------------------
__global__ void vq_finalize_kernel(float* __restrict__ out, int nd) {
    __shared__ float sh[256];
    float s = 0.0f;
    for (int k = threadIdx.x; k < KCB; k += 256) {
        if (g_active[k] == 0) s += dec_f(g_class_min[k]);
    }
    sh[threadIdx.x] = s;
    __syncthreads();
    for (int o = 128; o; o >>= 1) {
        if (threadIdx.x < o) sh[threadIdx.x] += sh[threadIdx.x + o];
        __syncthreads();
    }
    if (threadIdx.x == 0) {
        float mse = g_mse / (float)((size_t)N_ROWS * DIM);
        float ent = sh[0] / (float)KCB;
        out[nd] = 1.25f * mse + 0.02f * ent;
    }
}

// ---------------- launcher ----------------------------------------------------
extern "C" void kernel_launch(void* const* d_in, const int* in_sizes, int n_in,
                              void* d_out, int out_size) {
    const float* x  = (const float*)d_in[0];
    const float* cb = (const float*)d_in[1];
    float* out = (float*)d_out;

    vq_init_kernel<<<(N_ROWS + 255) / 256, 256>>>();
    vq_sqsum_kernel<<<N_ROWS / 8, 256>>>(x, N_ROWS, 0);
    vq_sqsum_kernel<<<KCB / 8, 256>>>(cb, KCB, 1);

    dim3 grid(KCB / BN, N_ROWS / BM);
    vq_gemm_kernel<<<grid, 256>>>(x, cb);

    vq_gather_kernel<<<N_ROWS / 8, 256>>>(x, cb, out);

    int nd = N_ROWS * DIM;
    vq_finalize_kernel<<<1, 256>>>(out, nd);
}

// round 6
// speedup vs baseline: 1.8533x; 1.8533x over previous
#include <cuda_runtime.h>
#include <cuda_bf16.h>
#include <cstdint>

// VectorQuantizer — single-pass bf16 HMMA GEMM + order-replicated fp32 refinement.
// inputs:  d_in[0] = inputs  [16,32,32,256] f32  (N=16384 rows, D=256)
//          d_in[1] = codebook [4096,256] f32     (K=4096)
// output:  d_out[0..N*D) = embeddings (straight-through), d_out[N*D] = loss

#define NR    16384
#define KCB   4096
#define DDIM  256
#define BM    128
#define BN    128
#define BK    32
#define NCH   (DDIM / BK)        // 8 k-chunks
#define ROWB  80u                // padded smem row bytes (64 data + 16 pad)
#define ARRB  (128u * ROWB)      // 10240 B per array
#define STGB  (2u * ARRB)        // 20480 B per stage (Ah, Bh)
#define SMEM_DYN (2 * STGB)      // 40960 B
#define EPS   0.25f

// ---------------- scratch (__device__ globals) -------------------------------
__device__ __nv_bfloat16 g_Ahi[NR * DDIM];
__device__ __nv_bfloat16 g_Bhi[KCB * DDIM];
__device__ unsigned int       g_rowmin_approx[NR];   // enc(d_red) per row
__device__ unsigned long long g_row_argmin[NR];      // (enc(d_full)<<32)|col
__device__ unsigned int       g_class_min[KCB];
__device__ int                g_active[KCB];
__device__ float              g_mse;
__device__ float              g_xsq[NR];
__device__ float              g_csq[KCB];

// ---------------- helpers ----------------------------------------------------
__device__ __forceinline__ unsigned int enc_f(float f) {
    unsigned int u = __float_as_uint(f);
    return (u & 0x80000000u) ? ~u : (u | 0x80000000u);
}
__device__ __forceinline__ float dec_f(unsigned int e) {
    return (e & 0x80000000u) ? __uint_as_float(e ^ 0x80000000u)
                             : __uint_as_float(~e);
}
__device__ __forceinline__ uint32_t smem_u32(const void* p) {
    uint32_t a;
    asm("{ .reg .u64 t; cvta.to.shared.u64 t, %1; cvt.u32.u64 %0, t; }"
        : "=r"(a) : "l"(p));
    return a;
}
__device__ __forceinline__ void cp16(uint32_t dst, const void* src) {
    asm volatile("cp.async.cg.shared.global [%0], [%1], 16;"
                 :: "r"(dst), "l"(src) : "memory");
}
#define CP_COMMIT() asm volatile("cp.async.commit_group;" ::: "memory")
#define CP_WAIT1()  asm volatile("cp.async.wait_group 1;" ::: "memory")
#define CP_WAIT0()  asm volatile("cp.async.wait_group 0;" ::: "memory")

__device__ __forceinline__ void ldsm4(uint32_t r[4], uint32_t addr) {
    asm volatile("ldmatrix.sync.aligned.m8n8.x4.shared.b16 {%0,%1,%2,%3}, [%4];"
                 : "=r"(r[0]), "=r"(r[1]), "=r"(r[2]), "=r"(r[3]) : "r"(addr));
}
__device__ __forceinline__ uint32_t lds32(uint32_t addr) {
    uint32_t v;
    asm volatile("ld.shared.b32 %0, [%1];" : "=r"(v) : "r"(addr));
    return v;
}
__device__ __forceinline__ void mma_bf16(float c[4], const uint32_t a[4],
                                         uint32_t b0, uint32_t b1) {
    asm volatile(
        "mma.sync.aligned.m16n8k16.row.col.f32.bf16.bf16.f32 "
        "{%0,%1,%2,%3}, {%4,%5,%6,%7}, {%8,%9}, {%0,%1,%2,%3};"
        : "+f"(c[0]), "+f"(c[1]), "+f"(c[2]), "+f"(c[3])
        : "r"(a[0]), "r"(a[1]), "r"(a[2]), "r"(a[3]), "r"(b0), "r"(b1));
}

// ---------------- init --------------------------------------------------------
__global__ void vq_init_kernel() {
    int i = blockIdx.x * blockDim.x + threadIdx.x;
    if (i < NR) { g_row_argmin[i] = 0xFFFFFFFFFFFFFFFFull; g_rowmin_approx[i] = 0xFFFFFFFFu; }
    if (i < KCB) { g_class_min[i] = 0xFFFFFFFFu; g_active[i] = 0; }
    if (i == 0) g_mse = 0.0f;
}

// ---------------- bf16 convert + squared norms -------------------------------
__global__ void vq_split_kernel(const float* __restrict__ src, int rows, int which) {
    int warp = threadIdx.x >> 5;
    int lane = threadIdx.x & 31;
    int row  = blockIdx.x * 8 + warp;
    if (row >= rows) return;
    __nv_bfloat16* hi = which ? g_Bhi : g_Ahi;
    float*         sq = which ? g_csq : g_xsq;
    const float4* s4 = reinterpret_cast<const float4*>(src + (size_t)row * DDIM);
    __nv_bfloat162* h2 = reinterpret_cast<__nv_bfloat162*>(hi + (size_t)row * DDIM);
    float acc = 0.0f;
#pragma unroll
    for (int j = lane; j < DDIM / 4; j += 32) {
        float4 v = s4[j];
        h2[2 * j]     = __nv_bfloat162(__float2bfloat16_rn(v.x), __float2bfloat16_rn(v.y));
        h2[2 * j + 1] = __nv_bfloat162(__float2bfloat16_rn(v.z), __float2bfloat16_rn(v.w));
        acc += v.x * v.x + v.y * v.y + v.z * v.z + v.w * v.w;
    }
#pragma unroll
    for (int o = 16; o; o >>= 1) acc += __shfl_xor_sync(0xFFFFFFFFu, acc, o);
    if (lane == 0) sq[row] = acc;
}

// ---------------- fused GEMM (single-pass bf16 HMMA) --------------------------
// CTA: 128x128, 512 threads = 16 warps in 4(M)x4(N); warp tile 32x32.
// PHASE 1: approx row-min (reduced dist) + per-class full-dist min.
// PHASE 2: candidate filter vs rowmin+EPS, fp32 recompute in round-1 op order.
template <int PHASE>
__global__ __launch_bounds__(512)
void vq_gemm(const float* __restrict__ xf, const float* __restrict__ cbf) {
    extern __shared__ char dynsm[];
    __shared__ unsigned int s_rowmin[BM];
    __shared__ unsigned int s_clsmin[BN];
    __shared__ float        s_xsq[BM];
    __shared__ float        s_csq[BN];

    const uint32_t sb = smem_u32(dynsm);
    const int tid  = threadIdx.x;
    const int lane = tid & 31;
    const int w    = tid >> 5;
    const int m_base = (w >> 2) * 32;
    const int n_base = (w & 3) * 32;
    const int tileM = blockIdx.y * BM;
    const int tileN = blockIdx.x * BN;

    if (tid < BM) {
        if (PHASE == 1) {
            s_rowmin[tid] = 0xFFFFFFFFu;
            s_clsmin[tid] = 0xFFFFFFFFu;
            s_xsq[tid] = g_xsq[tileM + tid];
        }
        s_csq[tid] = g_csq[tileN + tid];
    }

    const __nv_bfloat16* Ah = g_Ahi + (size_t)tileM * DDIM;
    const __nv_bfloat16* Bh = g_Bhi + (size_t)tileN * DDIM;

    float c[2][4][4];
#pragma unroll
    for (int mt = 0; mt < 2; mt++)
#pragma unroll
        for (int nt = 0; nt < 4; nt++)
#pragma unroll
            for (int r = 0; r < 4; r++) c[mt][nt][r] = 0.0f;

    // loader: per stage 2 arrays x 128 rows x 4 chunks(16B) = 1024 cp16 / 512 thr
    const int lrow = tid >> 2;
    const int lch  = tid & 3;
    const uint32_t ldst = (uint32_t)lrow * ROWB + (uint32_t)lch * 16u;
    const size_t lsrc = (size_t)lrow * DDIM + lch * 8;

#define LOAD_CHUNK(stg, k0)                                   \
    do {                                                      \
        uint32_t st_ = sb + (stg) * STGB;                     \
        cp16(st_ + ldst,        Ah + lsrc + (k0));            \
        cp16(st_ + ARRB + ldst, Bh + lsrc + (k0));            \
        CP_COMMIT();                                          \
    } while (0)

    LOAD_CHUNK(0u, 0);

    const uint32_t arow = (uint32_t)(m_base + (lane & 7) + 8 * ((lane >> 3) & 1));
    const uint32_t acol16 = 16u * (uint32_t)(lane >> 4);
    const uint32_t brow = (uint32_t)(n_base + (lane >> 2));
    const uint32_t bcol = 4u * (uint32_t)(lane & 3);

    for (int ch = 0; ch < NCH; ch++) {
        if (ch + 1 < NCH) {
            LOAD_CHUNK((uint32_t)((ch + 1) & 1), (ch + 1) * BK);
            CP_WAIT1();
        } else {
            CP_WAIT0();
        }
        __syncthreads();

        const uint32_t st = sb + (uint32_t)(ch & 1) * STGB;
#pragma unroll
        for (int s16 = 0; s16 < 2; s16++) {
            uint32_t ah[2][4];
#pragma unroll
            for (int mt = 0; mt < 2; mt++) {
                uint32_t ra = (arow + 16u * mt) * ROWB + (uint32_t)(s16 * 32) + acol16;
                ldsm4(ah[mt], st + ra);
            }
#pragma unroll
            for (int nt = 0; nt < 4; nt++) {
                uint32_t rb = (brow + 8u * nt) * ROWB + (uint32_t)(s16 * 32) + bcol;
                uint32_t bh0 = lds32(st + ARRB + rb);
                uint32_t bh1 = lds32(st + ARRB + rb + 16u);
#pragma unroll
                for (int mt = 0; mt < 2; mt++)
                    mma_bf16(c[mt][nt], ah[mt], bh0, bh1);
            }
        }
        __syncthreads();
    }

    // ---- epilogue ----
    if (PHASE == 1) {
        unsigned int er[2][4][4], ef[2][4][4];
#pragma unroll
        for (int mt = 0; mt < 2; mt++)
#pragma unroll
            for (int nt = 0; nt < 4; nt++)
#pragma unroll
                for (int h = 0; h < 2; h++) {
                    int rl = m_base + mt * 16 + (lane >> 2) + 8 * h;
#pragma unroll
                    for (int b = 0; b < 2; b++) {
                        int cl = n_base + nt * 8 + 2 * (lane & 3) + b;
                        float dred = fmaf(-2.0f, c[mt][nt][h * 2 + b], s_csq[cl]);
                        er[mt][nt][h * 2 + b] = enc_f(dred);
                        ef[mt][nt][h * 2 + b] = enc_f(dred + s_xsq[rl]);
                    }
                }
        // row-min of reduced dist (quads)
#pragma unroll
        for (int mt = 0; mt < 2; mt++)
#pragma unroll
            for (int h = 0; h < 2; h++) {
                int rl = m_base + mt * 16 + (lane >> 2) + 8 * h;
                unsigned int best = 0xFFFFFFFFu;
#pragma unroll
                for (int nt = 0; nt < 4; nt++)
#pragma unroll
                    for (int b = 0; b < 2; b++) {
                        unsigned int v = er[mt][nt][h * 2 + b];
                        if (v < best) best = v;
                    }
#pragma unroll
                for (int o = 1; o <= 2; o <<= 1) {
                    unsigned int t = __shfl_xor_sync(0xFFFFFFFFu, best, o);
                    if (t < best) best = t;
                }
                if ((lane & 3) == 0) atomicMin(&s_rowmin[rl], best);
            }
        // per-class min of full dist
#pragma unroll
        for (int nt = 0; nt < 4; nt++)
#pragma unroll
            for (int b = 0; b < 2; b++) {
                unsigned int cm = 0xFFFFFFFFu;
#pragma unroll
                for (int mt = 0; mt < 2; mt++)
#pragma unroll
                    for (int h = 0; h < 2; h++) {
                        unsigned int v = ef[mt][nt][h * 2 + b];
                        if (v < cm) cm = v;
                    }
#pragma unroll
                for (int o = 4; o <= 16; o <<= 1) {
                    unsigned int t = __shfl_xor_sync(0xFFFFFFFFu, cm, o);
                    if (t < cm) cm = t;
                }
                if (lane < 4) atomicMin(&s_clsmin[n_base + nt * 8 + 2 * lane + b], cm);
            }
        __syncthreads();
        if (tid < BM) {
            atomicMin(&g_rowmin_approx[tileM + tid], s_rowmin[tid]);
            atomicMin(&g_class_min[tileN + tid], s_clsmin[tid]);
        }
    } else {
        // PHASE 2: candidate filter + fp32 recompute replicating round-1 op order:
        // single accumulator, strictly sequential k, then fmaf(-2, dot, xsq+csq).
#pragma unroll
        for (int mt = 0; mt < 2; mt++)
#pragma unroll
            for (int h = 0; h < 2; h++) {
                const int rl = m_base + mt * 16 + (lane >> 2) + 8 * h;
                const int row = tileM + rl;
                const float thr = dec_f(g_rowmin_approx[row]) + EPS;
#pragma unroll
                for (int nt = 0; nt < 4; nt++)
#pragma unroll
                    for (int b = 0; b < 2; b++) {
                        const int cl = n_base + nt * 8 + 2 * (lane & 3) + b;
                        float dred = fmaf(-2.0f, c[mt][nt][h * 2 + b], s_csq[cl]);
                        if (dred <= thr) {
                            const int col = tileN + cl;
                            const float4* xr =
                                reinterpret_cast<const float4*>(xf + (size_t)row * DDIM);
                            const float4* cr =
                                reinterpret_cast<const float4*>(cbf + (size_t)col * DDIM);
                            float dot = 0.0f;     // sequential k-order, one accumulator
#pragma unroll 8
                            for (int k = 0; k < DDIM / 4; k++) {
                                float4 a = xr[k];
                                float4 v = cr[k];
                                dot = fmaf(a.x, v.x, dot);
                                dot = fmaf(a.y, v.y, dot);
                                dot = fmaf(a.z, v.z, dot);
                                dot = fmaf(a.w, v.w, dot);
                            }
                            float dfull = fmaf(-2.0f, dot, g_xsq[row] + s_csq[cl]);
                            unsigned long long pk =
                                ((unsigned long long)enc_f(dfull) << 32) |
                                (unsigned int)col;
                            atomicMin(&g_row_argmin[row], pk);
                        }
                    }
            }
    }
}

// ---------------- gather + MSE + active flags --------------------------------
__global__ void vq_gather_kernel(const float* __restrict__ x,
                                 const float* __restrict__ cb,
                                 float* __restrict__ out) {
    int warp = threadIdx.x >> 5;
    int lane = threadIdx.x & 31;
    int row  = blockIdx.x * 8 + warp;
    float s = 0.0f;
    if (row < NR) {
        unsigned int tok = (unsigned int)(g_row_argmin[row] & 0xFFFFFFFFull);
        if (lane == 0) g_active[tok] = 1;
        const float4* cp = reinterpret_cast<const float4*>(cb + (size_t)tok * DDIM);
        const float4* xp = reinterpret_cast<const float4*>(x + (size_t)row * DDIM);
        float4*       op = reinterpret_cast<float4*>(out + (size_t)row * DDIM);
#pragma unroll
    for (int j = lane; j < DDIM / 4; j += 32) {
            float4 cc = cp[j];
            float4 v  = xp[j];
            op[j] = cc;
            float dx = cc.x - v.x, dy = cc.y - v.y, dz = cc.z - v.z, dw = cc.w - v.w;
            s += dx * dx + dy * dy + dz * dz + dw * dw;
        }
    }
#pragma unroll
    for (int o = 16; o; o >>= 1) s += __shfl_xor_sync(0xFFFFFFFFu, s, o);
    __shared__ float ws[8];
    if (lane == 0) ws[warp] = s;
    __syncthreads();
    if (threadIdx.x == 0) {
        float t = 0.0f;
#pragma unroll
        for (int w2 = 0; w2 < 8; w2++) t += ws[w2];
        atomicAdd(&g_mse, t);
    }
}

// ---------------- finalize loss ----------------------------------------------
__global__ void vq_finalize_kernel(float* __restrict__ out, int nd) {
    __shared__ float sh[256];
    float s = 0.0f;
    for (int k = threadIdx.x; k < KCB; k += 256) {
        if (g_active[k] == 0) s += dec_f(g_class_min[k]);
    }
    sh[threadIdx.x] = s;
    __syncthreads();
    for (int o = 128; o; o >>= 1) {
        if (threadIdx.x < o) sh[threadIdx.x] += sh[threadIdx.x + o];
        __syncthreads();
    }
    if (threadIdx.x == 0) {
        float mse = g_mse / (float)((size_t)NR * DDIM);
        float ent = sh[0] / (float)KCB;
        out[nd] = 1.25f * mse + 0.02f * ent;
    }
}

// ---------------- launcher ----------------------------------------------------
extern "C" void kernel_launch(void* const* d_in, const int* in_sizes, int n_in,
                              void* d_out, int out_size) {
    const float* x  = (const float*)d_in[0];
    const float* cb = (const float*)d_in[1];
    float* out = (float*)d_out;

    cudaFuncSetAttribute(vq_gemm<1>,
                         cudaFuncAttributeMaxDynamicSharedMemorySize, SMEM_DYN);
    cudaFuncSetAttribute(vq_gemm<2>,
                         cudaFuncAttributeMaxDynamicSharedMemorySize, SMEM_DYN);

    vq_init_kernel<<<(NR + 255) / 256, 256>>>();
    vq_split_kernel<<<NR / 8, 256>>>(x, NR, 0);
    vq_split_kernel<<<KCB / 8, 256>>>(cb, KCB, 1);

    dim3 grid(KCB / BN, NR / BM);   // (32, 128) = 4096 CTAs
    vq_gemm<1><<<grid, 512, SMEM_DYN>>>(x, cb);
    vq_gemm<2><<<grid, 512, SMEM_DYN>>>(x, cb);

    vq_gather_kernel<<<NR / 8, 256>>>(x, cb, out);
    vq_finalize_kernel<<<1, 256>>>(out, NR * DDIM);
}

// round 7
// speedup vs baseline: 2.1468x; 1.1584x over previous
#include <cuda_runtime.h>
#include <cuda_bf16.h>
#include <cstdint>

// VectorQuantizer — bf16 HMMA GEMM (writes approx dists) + exact refinement pass.
// inputs:  d_in[0] = inputs  [16,32,32,256] f32  (N=16384 rows, D=256)
//          d_in[1] = codebook [4096,256] f32     (K=4096)
// output:  d_out[0..N*D) = embeddings (straight-through), d_out[N*D] = loss

#define NR    16384
#define KCB   4096
#define DDIM  256
#define BM    128
#define BN    128
#define BK    32
#define NCH   (DDIM / BK)        // 8 k-chunks
#define ROWB  80u                // padded smem row bytes (64 data + 16 pad)
#define ARRB  (128u * ROWB)      // 10240 B per array
#define STGB  (2u * ARRB)        // 20480 B per stage (Ah, Bh)
#define NSTG  3
#define SMEM_DYN (NSTG * STGB)   // 61440 B
#define EPS   0.15f

// ---------------- scratch (__device__ globals) -------------------------------
__device__ __nv_bfloat16 g_Ahi[NR * DDIM];
__device__ __nv_bfloat16 g_Bhi[KCB * DDIM];
__device__ __nv_bfloat162 g_dist2[NR * KCB / 2];     // approx reduced dists (bf16)
__device__ unsigned int       g_rowmin_approx[NR];   // enc(d_red) per row
__device__ unsigned long long g_row_argmin[NR];      // (enc(d_full)<<32)|col
__device__ unsigned int       g_class_min[KCB];
__device__ int                g_active[KCB];
__device__ float              g_mse;
__device__ float              g_xsq[NR];
__device__ float              g_csq[KCB];

// ---------------- helpers ----------------------------------------------------
__device__ __forceinline__ unsigned int enc_f(float f) {
    unsigned int u = __float_as_uint(f);
    return (u & 0x80000000u) ? ~u : (u | 0x80000000u);
}
__device__ __forceinline__ float dec_f(unsigned int e) {
    return (e & 0x80000000u) ? __uint_as_float(e ^ 0x80000000u)
                             : __uint_as_float(~e);
}
__device__ __forceinline__ uint32_t smem_u32(const void* p) {
    uint32_t a;
    asm("{ .reg .u64 t; cvta.to.shared.u64 t, %1; cvt.u32.u64 %0, t; }"
        : "=r"(a) : "l"(p));
    return a;
}
__device__ __forceinline__ void cp16(uint32_t dst, const void* src) {
    asm volatile("cp.async.cg.shared.global [%0], [%1], 16;"
                 :: "r"(dst), "l"(src) : "memory");
}
#define CP_COMMIT() asm volatile("cp.async.commit_group;" ::: "memory")
#define CP_WAIT1()  asm volatile("cp.async.wait_group 1;" ::: "memory")
#define CP_WAIT0()  asm volatile("cp.async.wait_group 0;" ::: "memory")

__device__ __forceinline__ void ldsm4(uint32_t r[4], uint32_t addr) {
    asm volatile("ldmatrix.sync.aligned.m8n8.x4.shared.b16 {%0,%1,%2,%3}, [%4];"
                 : "=r"(r[0]), "=r"(r[1]), "=r"(r[2]), "=r"(r[3]) : "r"(addr));
}
__device__ __forceinline__ uint32_t lds32(uint32_t addr) {
    uint32_t v;
    asm volatile("ld.shared.b32 %0, [%1];" : "=r"(v) : "r"(addr));
    return v;
}
__device__ __forceinline__ void mma_bf16(float c[4], const uint32_t a[4],
                                         uint32_t b0, uint32_t b1) {
    asm volatile(
        "mma.sync.aligned.m16n8k16.row.col.f32.bf16.bf16.f32 "
        "{%0,%1,%2,%3}, {%4,%5,%6,%7}, {%8,%9}, {%0,%1,%2,%3};"
        : "+f"(c[0]), "+f"(c[1]), "+f"(c[2]), "+f"(c[3])
        : "r"(a[0]), "r"(a[1]), "r"(a[2]), "r"(a[3]), "r"(b0), "r"(b1));
}

// ---------------- init --------------------------------------------------------
__global__ void vq_init_kernel() {
    int i = blockIdx.x * blockDim.x + threadIdx.x;
    if (i < NR) { g_row_argmin[i] = 0xFFFFFFFFFFFFFFFFull; g_rowmin_approx[i] = 0xFFFFFFFFu; }
    if (i < KCB) { g_class_min[i] = 0xFFFFFFFFu; g_active[i] = 0; }
    if (i == 0) g_mse = 0.0f;
}

// ---------------- bf16 convert + squared norms -------------------------------
__global__ void vq_split_kernel(const float* __restrict__ src, int rows, int which) {
    int warp = threadIdx.x >> 5;
    int lane = threadIdx.x & 31;
    int row  = blockIdx.x * 8 + warp;
    if (row >= rows) return;
    __nv_bfloat16* hi = which ? g_Bhi : g_Ahi;
    float*         sq = which ? g_csq : g_xsq;
    const float4* s4 = reinterpret_cast<const float4*>(src + (size_t)row * DDIM);
    __nv_bfloat162* h2 = reinterpret_cast<__nv_bfloat162*>(hi + (size_t)row * DDIM);
    float acc = 0.0f;
#pragma unroll
    for (int j = lane; j < DDIM / 4; j += 32) {
        float4 v = s4[j];
        h2[2 * j]     = __nv_bfloat162(__float2bfloat16_rn(v.x), __float2bfloat16_rn(v.y));
        h2[2 * j + 1] = __nv_bfloat162(__float2bfloat16_rn(v.z), __float2bfloat16_rn(v.w));
        acc += v.x * v.x + v.y * v.y + v.z * v.z + v.w * v.w;
    }
#pragma unroll
    for (int o = 16; o; o >>= 1) acc += __shfl_xor_sync(0xFFFFFFFFu, acc, o);
    if (lane == 0) sq[row] = acc;
}

// ---------------- fused GEMM (single-pass bf16 HMMA, 3-stage pipeline) --------
// CTA: 128x128, 512 threads = 16 warps in 4(M)x4(N); warp tile 32x32.
// Outputs: approx row-min, per-class full-dist min, bf16 reduced dists.
__global__ __launch_bounds__(512)
void vq_gemm() {
    extern __shared__ char dynsm[];
    __shared__ unsigned int s_rowmin[BM];
    __shared__ unsigned int s_clsmin[BN];
    __shared__ float        s_xsq[BM];
    __shared__ float        s_csq[BN];

    const uint32_t sb = smem_u32(dynsm);
    const int tid  = threadIdx.x;
    const int lane = tid & 31;
    const int w    = tid >> 5;
    const int m_base = (w >> 2) * 32;
    const int n_base = (w & 3) * 32;
    const int tileM = blockIdx.y * BM;
    const int tileN = blockIdx.x * BN;

    if (tid < BM) {
        s_rowmin[tid] = 0xFFFFFFFFu;
        s_clsmin[tid] = 0xFFFFFFFFu;
        s_xsq[tid] = g_xsq[tileM + tid];
        s_csq[tid] = g_csq[tileN + tid];
    }

    const __nv_bfloat16* Ah = g_Ahi + (size_t)tileM * DDIM;
    const __nv_bfloat16* Bh = g_Bhi + (size_t)tileN * DDIM;

    float c[2][4][4];
#pragma unroll
    for (int mt = 0; mt < 2; mt++)
#pragma unroll
        for (int nt = 0; nt < 4; nt++)
#pragma unroll
            for (int r = 0; r < 4; r++) c[mt][nt][r] = 0.0f;

    // loader: per stage 2 arrays x 128 rows x 4 chunks(16B) = 1024 cp16 / 512 thr
    const int lrow = tid >> 2;
    const int lch  = tid & 3;
    const uint32_t ldst = (uint32_t)lrow * ROWB + (uint32_t)lch * 16u;
    const size_t lsrc = (size_t)lrow * DDIM + lch * 8;

#define LOAD_CHUNK(stg, k0)                                   \
    do {                                                      \
        uint32_t st_ = sb + (uint32_t)(stg) * STGB;           \
        cp16(st_ + ldst,        Ah + lsrc + (k0));            \
        cp16(st_ + ARRB + ldst, Bh + lsrc + (k0));            \
        CP_COMMIT();                                          \
    } while (0)

    LOAD_CHUNK(0, 0);
    LOAD_CHUNK(1, BK);

    const uint32_t arow = (uint32_t)(m_base + (lane & 7) + 8 * ((lane >> 3) & 1));
    const uint32_t acol16 = 16u * (uint32_t)(lane >> 4);
    const uint32_t brow = (uint32_t)(n_base + (lane >> 2));
    const uint32_t bcol = 4u * (uint32_t)(lane & 3);

#pragma unroll
    for (int ch = 0; ch < NCH; ch++) {
        // ensure chunk ch's group is complete (groups retire in order)
        if (ch < NCH - 1) { CP_WAIT1(); } else { CP_WAIT0(); }
        __syncthreads();   // all warps done with chunk ch-1 -> its stage is free
        if (ch + 2 < NCH) LOAD_CHUNK((ch + 2) % NSTG, (ch + 2) * BK);

        const uint32_t st = sb + (uint32_t)(ch % NSTG) * STGB;
#pragma unroll
        for (int s16 = 0; s16 < 2; s16++) {
            uint32_t ah[2][4];
#pragma unroll
            for (int mt = 0; mt < 2; mt++) {
                uint32_t ra = (arow + 16u * mt) * ROWB + (uint32_t)(s16 * 32) + acol16;
                ldsm4(ah[mt], st + ra);
            }
#pragma unroll
            for (int nt = 0; nt < 4; nt++) {
                uint32_t rb = (brow + 8u * nt) * ROWB + (uint32_t)(s16 * 32) + bcol;
                uint32_t bh0 = lds32(st + ARRB + rb);
                uint32_t bh1 = lds32(st + ARRB + rb + 16u);
#pragma unroll
                for (int mt = 0; mt < 2; mt++)
                    mma_bf16(c[mt][nt], ah[mt], bh0, bh1);
            }
        }
    }

    // ---- epilogue: dred, store bf16 dists, row-min, per-class min ----
    unsigned int er[2][4][4], ef[2][4][4];
#pragma unroll
    for (int mt = 0; mt < 2; mt++)
#pragma unroll
        for (int nt = 0; nt < 4; nt++)
#pragma unroll
            for (int h = 0; h < 2; h++) {
                int rl = m_base + mt * 16 + (lane >> 2) + 8 * h;
                float dr[2];
#pragma unroll
                for (int b = 0; b < 2; b++) {
                    int cl = n_base + nt * 8 + 2 * (lane & 3) + b;
                    float dred = fmaf(-2.0f, c[mt][nt][h * 2 + b], s_csq[cl]);
                    dr[b] = dred;
                    er[mt][nt][h * 2 + b] = enc_f(dred);
                    ef[mt][nt][h * 2 + b] = enc_f(dred + s_xsq[rl]);
                }
                const int row = tileM + rl;
                const int col0 = tileN + n_base + nt * 8 + 2 * (lane & 3);
                g_dist2[((size_t)row * KCB + col0) >> 1] =
                    __nv_bfloat162(__float2bfloat16_rn(dr[0]),
                                   __float2bfloat16_rn(dr[1]));
            }
    // row-min of reduced dist (quads)
#pragma unroll
    for (int mt = 0; mt < 2; mt++)
#pragma unroll
        for (int h = 0; h < 2; h++) {
            int rl = m_base + mt * 16 + (lane >> 2) + 8 * h;
            unsigned int best = 0xFFFFFFFFu;
#pragma unroll
            for (int nt = 0; nt < 4; nt++)
#pragma unroll
                for (int b = 0; b < 2; b++) {
                    unsigned int v = er[mt][nt][h * 2 + b];
                    if (v < best) best = v;
                }
#pragma unroll
            for (int o = 1; o <= 2; o <<= 1) {
                unsigned int t = __shfl_xor_sync(0xFFFFFFFFu, best, o);
                if (t < best) best = t;
            }
            if ((lane & 3) == 0) atomicMin(&s_rowmin[rl], best);
        }
    // per-class min of full dist
#pragma unroll
    for (int nt = 0; nt < 4; nt++)
#pragma unroll
        for (int b = 0; b < 2; b++) {
            unsigned int cm = 0xFFFFFFFFu;
#pragma unroll
            for (int mt = 0; mt < 2; mt++)
#pragma unroll
                for (int h = 0; h < 2; h++) {
                    unsigned int v = ef[mt][nt][h * 2 + b];
                    if (v < cm) cm = v;
                }
#pragma unroll
            for (int o = 4; o <= 16; o <<= 1) {
                unsigned int t = __shfl_xor_sync(0xFFFFFFFFu, cm, o);
                if (t < cm) cm = t;
            }
            if (lane < 4) atomicMin(&s_clsmin[n_base + nt * 8 + 2 * lane + b], cm);
        }
    __syncthreads();
    if (tid < BM) {
        atomicMin(&g_rowmin_approx[tileM + tid], s_rowmin[tid]);
        atomicMin(&g_class_min[tileN + tid], s_clsmin[tid]);
    }
}

// ---------------- refinement: scan bf16 dists, exact fp32 on candidates -------
// 1 warp per row; exact dot replicates round-1 op order (single acc, seq k).
__global__ __launch_bounds__(256)
void vq_refine(const float* __restrict__ xf, const float* __restrict__ cbf) {
    const int warp = threadIdx.x >> 5;
    const int lane = threadIdx.x & 31;
    const int row  = blockIdx.x * 8 + warp;
    if (row >= NR) return;

    const float thr = dec_f(g_rowmin_approx[row]) + EPS;
    const uint4* dp = reinterpret_cast<const uint4*>(
        g_dist2 + (size_t)row * (KCB / 2));

#pragma unroll 4
    for (int j = lane; j < KCB / 8; j += 32) {
        uint4 v = dp[j];
        const uint32_t pk[4] = {v.x, v.y, v.z, v.w};
#pragma unroll
        for (int q = 0; q < 4; q++) {
            float2 f = __bfloat1622float2(*reinterpret_cast<const __nv_bfloat162*>(&pk[q]));
#pragma unroll
            for (int b = 0; b < 2; b++) {
                float dv = (b == 0) ? f.x : f.y;
                if (dv <= thr) {
                    const int col = j * 8 + q * 2 + b;
                    const float4* xr =
                        reinterpret_cast<const float4*>(xf + (size_t)row * DDIM);
                    const float4* cr =
                        reinterpret_cast<const float4*>(cbf + (size_t)col * DDIM);
                    float dot = 0.0f;     // sequential k-order, one accumulator
#pragma unroll 8
                    for (int k = 0; k < DDIM / 4; k++) {
                        float4 a = xr[k];
                        float4 u = cr[k];
                        dot = fmaf(a.x, u.x, dot);
                        dot = fmaf(a.y, u.y, dot);
                        dot = fmaf(a.z, u.z, dot);
                        dot = fmaf(a.w, u.w, dot);
                    }
                    float dfull = fmaf(-2.0f, dot, g_xsq[row] + g_csq[col]);
                    unsigned long long p =
                        ((unsigned long long)enc_f(dfull) << 32) |
                        (unsigned int)col;
                    atomicMin(&g_row_argmin[row], p);
                }
            }
        }
    }
}

// ---------------- gather + MSE + active flags --------------------------------
__global__ void vq_gather_kernel(const float* __restrict__ x,
                                 const float* __restrict__ cb,
                                 float* __restrict__ out) {
    int warp = threadIdx.x >> 5;
    int lane = threadIdx.x & 31;
    int row  = blockIdx.x * 8 + warp;
    float s = 0.0f;
    if (row < NR) {
        unsigned int tok = (unsigned int)(g_row_argmin[row] & 0xFFFFFFFFull);
        if (lane == 0) g_active[tok] = 1;
        const float4* cp = reinterpret_cast<const float4*>(cb + (size_t)tok * DDIM);
        const float4* xp = reinterpret_cast<const float4*>(x + (size_t)row * DDIM);
        float4*       op = reinterpret_cast<float4*>(out + (size_t)row * DDIM);
#pragma unroll
        for (int j = lane; j < DDIM / 4; j += 32) {
            float4 cc = cp[j];
            float4 v  = xp[j];
            op[j] = cc;
            float dx = cc.x - v.x, dy = cc.y - v.y, dz = cc.z - v.z, dw = cc.w - v.w;
            s += dx * dx + dy * dy + dz * dz + dw * dw;
        }
    }
#pragma unroll
    for (int o = 16; o; o >>= 1) s += __shfl_xor_sync(0xFFFFFFFFu, s, o);
    __shared__ float ws[8];
    if (lane == 0) ws[warp] = s;
    __syncthreads();
    if (threadIdx.x == 0) {
        float t = 0.0f;
#pragma unroll
        for (int w2 = 0; w2 < 8; w2++) t += ws[w2];
        atomicAdd(&g_mse, t);
    }
}

// ---------------- finalize loss ----------------------------------------------
__global__ void vq_finalize_kernel(float* __restrict__ out, int nd) {
    __shared__ float sh[256];
    float s = 0.0f;
    for (int k = threadIdx.x; k < KCB; k += 256) {
        if (g_active[k] == 0) s += dec_f(g_class_min[k]);
    }
    sh[threadIdx.x] = s;
    __syncthreads();
    for (int o = 128; o; o >>= 1) {
        if (threadIdx.x < o) sh[threadIdx.x] += sh[threadIdx.x + o];
        __syncthreads();
    }
    if (threadIdx.x == 0) {
        float mse = g_mse / (float)((size_t)NR * DDIM);
        float ent = sh[0] / (float)KCB;
        out[nd] = 1.25f * mse + 0.02f * ent;
    }
}

// ---------------- launcher ----------------------------------------------------
extern "C" void kernel_launch(void* const* d_in, const int* in_sizes, int n_in,
                              void* d_out, int out_size) {
    const float* x  = (const float*)d_in[0];
    const float* cb = (const float*)d_in[1];
    float* out = (float*)d_out;

    cudaFuncSetAttribute(vq_gemm,
                         cudaFuncAttributeMaxDynamicSharedMemorySize, SMEM_DYN);

    vq_init_kernel<<<(NR + 255) / 256, 256>>>();
    vq_split_kernel<<<NR / 8, 256>>>(x, NR, 0);
    vq_split_kernel<<<KCB / 8, 256>>>(cb, KCB, 1);

    dim3 grid(KCB / BN, NR / BM);   // (32, 128) = 4096 CTAs
    vq_gemm<<<grid, 512, SMEM_DYN>>>();

    vq_refine<<<NR / 8, 256>>>(x, cb);
    vq_gather_kernel<<<NR / 8, 256>>>(x, cb, out);
    vq_finalize_kernel<<<1, 256>>>(out, NR * DDIM);
}

// round 9
// speedup vs baseline: 2.3058x; 1.0741x over previous
#include <cuda_runtime.h>
#include <cuda_bf16.h>
#include <cstdint>

// VectorQuantizer — bf16 HMMA GEMM (writes approx dists) + fused exact refine/gather.
// inputs:  d_in[0] = inputs  [16,32,32,256] f32  (N=16384 rows, D=256)
//          d_in[1] = codebook [4096,256] f32     (K=4096)
// output:  d_out[0..N*D) = embeddings (straight-through), d_out[N*D] = loss

#define NR    16384
#define KCB   4096
#define DDIM  256
#define BM    128
#define BN    128
#define BK    32
#define NCH   (DDIM / BK)        // 8 k-chunks
#define ROWB  80u                // padded smem row bytes (64 data + 16 pad)
#define ARRB  (128u * ROWB)      // 10240 B per array
#define STGB  (2u * ARRB)        // 20480 B per stage (Ah, Bh)
#define SMEM_DYN (2 * STGB)      // 40960 B
#define EPS   0.15f

// ---------------- scratch (__device__ globals) -------------------------------
__device__ __nv_bfloat16 g_Ahi[NR * DDIM];
__device__ __nv_bfloat16 g_Bhi[KCB * DDIM];
__device__ __nv_bfloat162 g_dist2[NR * KCB / 2];     // approx reduced dists (bf16)
__device__ unsigned int   g_rowmin_approx[NR];       // enc(d_red) per row
__device__ unsigned int   g_class_min[KCB];
__device__ int            g_active[KCB];
__device__ float          g_mse;
__device__ float          g_xsq[NR];
__device__ float          g_csq[KCB];

// ---------------- helpers ----------------------------------------------------
__device__ __forceinline__ unsigned int enc_f(float f) {
    unsigned int u = __float_as_uint(f);
    return (u & 0x80000000u) ? ~u : (u | 0x80000000u);
}
__device__ __forceinline__ float dec_f(unsigned int e) {
    return (e & 0x80000000u) ? __uint_as_float(e ^ 0x80000000u)
                             : __uint_as_float(~e);
}
__device__ __forceinline__ uint32_t smem_u32(const void* p) {
    uint32_t a;
    asm("{ .reg .u64 t; cvta.to.shared.u64 t, %1; cvt.u32.u64 %0, t; }"
        : "=r"(a) : "l"(p));
    return a;
}
__device__ __forceinline__ void cp16(uint32_t dst, const void* src) {
    asm volatile("cp.async.cg.shared.global [%0], [%1], 16;"
                 :: "r"(dst), "l"(src) : "memory");
}
#define CP_COMMIT() asm volatile("cp.async.commit_group;" ::: "memory")
#define CP_WAIT1()  asm volatile("cp.async.wait_group 1;" ::: "memory")
#define CP_WAIT0()  asm volatile("cp.async.wait_group 0;" ::: "memory")

__device__ __forceinline__ void ldsm4(uint32_t r[4], uint32_t addr) {
    asm volatile("ldmatrix.sync.aligned.m8n8.x4.shared.b16 {%0,%1,%2,%3}, [%4];"
                 : "=r"(r[0]), "=r"(r[1]), "=r"(r[2]), "=r"(r[3]) : "r"(addr));
}
__device__ __forceinline__ uint32_t lds32(uint32_t addr) {
    uint32_t v;
    asm volatile("ld.shared.b32 %0, [%1];" : "=r"(v) : "r"(addr));
    return v;
}
__device__ __forceinline__ void mma_bf16(float c[4], const uint32_t a[4],
                                         uint32_t b0, uint32_t b1) {
    asm volatile(
        "mma.sync.aligned.m16n8k16.row.col.f32.bf16.bf16.f32 "
        "{%0,%1,%2,%3}, {%4,%5,%6,%7}, {%8,%9}, {%0,%1,%2,%3};"
        : "+f"(c[0]), "+f"(c[1]), "+f"(c[2]), "+f"(c[3])
        : "r"(a[0]), "r"(a[1]), "r"(a[2]), "r"(a[3]), "r"(b0), "r"(b1));
}

// ---------------- init --------------------------------------------------------
__global__ void vq_init_kernel() {
    int i = blockIdx.x * blockDim.x + threadIdx.x;
    if (i < NR) g_rowmin_approx[i] = 0xFFFFFFFFu;
    if (i < KCB) { g_class_min[i] = 0xFFFFFFFFu; g_active[i] = 0; }
    if (i == 0) g_mse = 0.0f;
}

// ---------------- bf16 convert + squared norms -------------------------------
__global__ void vq_split_kernel(const float* __restrict__ src, int rows, int which) {
    int warp = threadIdx.x >> 5;
    int lane = threadIdx.x & 31;
    int row  = blockIdx.x * 8 + warp;
    if (row >= rows) return;
    __nv_bfloat16* hi = which ? g_Bhi : g_Ahi;
    float*         sq = which ? g_csq : g_xsq;
    const float4* s4 = reinterpret_cast<const float4*>(src + (size_t)row * DDIM);
    __nv_bfloat162* h2 = reinterpret_cast<__nv_bfloat162*>(hi + (size_t)row * DDIM);
    float acc = 0.0f;
#pragma unroll
    for (int j = lane; j < DDIM / 4; j += 32) {
        float4 v = s4[j];
        h2[2 * j]     = __nv_bfloat162(__float2bfloat16_rn(v.x), __float2bfloat16_rn(v.y));
        h2[2 * j + 1] = __nv_bfloat162(__float2bfloat16_rn(v.z), __float2bfloat16_rn(v.w));
        acc += v.x * v.x + v.y * v.y + v.z * v.z + v.w * v.w;
    }
#pragma unroll
    for (int o = 16; o; o >>= 1) acc += __shfl_xor_sync(0xFFFFFFFFu, acc, o);
    if (lane == 0) sq[row] = acc;
}

// ---------------- fused GEMM (single-pass bf16 HMMA, 2-stage, 2 CTA/SM) -------
// CTA: 128x128, 512 threads = 16 warps in 4(M)x4(N); warp tile 32x32.
// Outputs: approx row-min, per-class full-dist min, bf16 reduced dists.
__global__ __launch_bounds__(512, 2)
void vq_gemm() {
    extern __shared__ char dynsm[];
    __shared__ unsigned int s_rowmin[BM];
    __shared__ unsigned int s_clsmin[BN];
    __shared__ float        s_xsq[BM];
    __shared__ float        s_csq[BN];

    const uint32_t sb = smem_u32(dynsm);
    const int tid  = threadIdx.x;
    const int lane = tid & 31;
    const int w    = tid >> 5;
    const int m_base = (w >> 2) * 32;
    const int n_base = (w & 3) * 32;
    const int tileM = blockIdx.y * BM;
    const int tileN = blockIdx.x * BN;

    if (tid < BM) {
        s_rowmin[tid] = 0xFFFFFFFFu;
        s_clsmin[tid] = 0xFFFFFFFFu;
        s_xsq[tid] = g_xsq[tileM + tid];
        s_csq[tid] = g_csq[tileN + tid];
    }

    const __nv_bfloat16* Ah = g_Ahi + (size_t)tileM * DDIM;
    const __nv_bfloat16* Bh = g_Bhi + (size_t)tileN * DDIM;

    float c[2][4][4];
#pragma unroll
    for (int mt = 0; mt < 2; mt++)
#pragma unroll
        for (int nt = 0; nt < 4; nt++)
#pragma unroll
            for (int r = 0; r < 4; r++) c[mt][nt][r] = 0.0f;

    // loader: per stage 2 arrays x 128 rows x 4 chunks(16B) = 1024 cp16 / 512 thr
    const int lrow = tid >> 2;
    const int lch  = tid & 3;
    const uint32_t ldst = (uint32_t)lrow * ROWB + (uint32_t)lch * 16u;
    const size_t lsrc = (size_t)lrow * DDIM + lch * 8;

#define LOAD_CHUNK(stg, k0)                                   \
    do {                                                      \
        uint32_t st_ = sb + (uint32_t)(stg) * STGB;           \
        cp16(st_ + ldst,        Ah + lsrc + (k0));            \
        cp16(st_ + ARRB + ldst, Bh + lsrc + (k0));            \
        CP_COMMIT();                                          \
    } while (0)

    LOAD_CHUNK(0u, 0);

    const uint32_t arow = (uint32_t)(m_base + (lane & 7) + 8 * ((lane >> 3) & 1));
    const uint32_t acol16 = 16u * (uint32_t)(lane >> 4);
    const uint32_t brow = (uint32_t)(n_base + (lane >> 2));
    const uint32_t bcol = 4u * (uint32_t)(lane & 3);

    for (int ch = 0; ch < NCH; ch++) {
        if (ch + 1 < NCH) {
            LOAD_CHUNK((uint32_t)((ch + 1) & 1), (ch + 1) * BK);
            CP_WAIT1();
        } else {
            CP_WAIT0();
        }
        __syncthreads();

        const uint32_t st = sb + (uint32_t)(ch & 1) * STGB;
#pragma unroll
        for (int s16 = 0; s16 < 2; s16++) {
            uint32_t ah[2][4];
#pragma unroll
            for (int mt = 0; mt < 2; mt++) {
                uint32_t ra = (arow + 16u * mt) * ROWB + (uint32_t)(s16 * 32) + acol16;
                ldsm4(ah[mt], st + ra);
            }
#pragma unroll
            for (int nt = 0; nt < 4; nt++) {
                uint32_t rb = (brow + 8u * nt) * ROWB + (uint32_t)(s16 * 32) + bcol;
                uint32_t bh0 = lds32(st + ARRB + rb);
                uint32_t bh1 = lds32(st + ARRB + rb + 16u);
#pragma unroll
                for (int mt = 0; mt < 2; mt++)
                    mma_bf16(c[mt][nt], ah[mt], bh0, bh1);
            }
        }
        __syncthreads();
    }

    // ---- epilogue (lean): dred, bf16 dist store, row-min, per-class min ----
    unsigned int cm[4][2];
#pragma unroll
    for (int nt = 0; nt < 4; nt++) { cm[nt][0] = 0xFFFFFFFFu; cm[nt][1] = 0xFFFFFFFFu; }

#pragma unroll
    for (int mt = 0; mt < 2; mt++)
#pragma unroll
        for (int h = 0; h < 2; h++) {
            const int rl = m_base + mt * 16 + (lane >> 2) + 8 * h;
            const int row = tileM + rl;
            const float xq = s_xsq[rl];
            unsigned int best = 0xFFFFFFFFu;
#pragma unroll
            for (int nt = 0; nt < 4; nt++) {
                float dr0, dr1;
                {
                    const int cl = n_base + nt * 8 + 2 * (lane & 3);
                    dr0 = fmaf(-2.0f, c[mt][nt][h * 2 + 0], s_csq[cl]);
                    dr1 = fmaf(-2.0f, c[mt][nt][h * 2 + 1], s_csq[cl + 1]);
                    unsigned int e0 = enc_f(dr0);
                    unsigned int e1 = enc_f(dr1);
                    if (e0 < best) best = e0;
                    if (e1 < best) best = e1;
                    unsigned int f0 = enc_f(dr0 + xq);
                    unsigned int f1 = enc_f(dr1 + xq);
                    if (f0 < cm[nt][0]) cm[nt][0] = f0;
                    if (f1 < cm[nt][1]) cm[nt][1] = f1;
                    const int col0 = tileN + cl;
                    g_dist2[((size_t)row * KCB + col0) >> 1] =
                        __nv_bfloat162(__float2bfloat16_rn(dr0),
                                       __float2bfloat16_rn(dr1));
                }
            }
#pragma unroll
            for (int o = 1; o <= 2; o <<= 1) {
                unsigned int t = __shfl_xor_sync(0xFFFFFFFFu, best, o);
                if (t < best) best = t;
            }
            if ((lane & 3) == 0) atomicMin(&s_rowmin[rl], best);
        }

#pragma unroll
    for (int nt = 0; nt < 4; nt++)
#pragma unroll
        for (int b = 0; b < 2; b++) {
            unsigned int v = cm[nt][b];
#pragma unroll
            for (int o = 4; o <= 16; o <<= 1) {
                unsigned int t = __shfl_xor_sync(0xFFFFFFFFu, v, o);
                if (t < v) v = t;
            }
            if (lane < 4) atomicMin(&s_clsmin[n_base + nt * 8 + 2 * lane + b], v);
        }

    __syncthreads();
    if (tid < BM) {
        atomicMin(&g_rowmin_approx[tileM + tid], s_rowmin[tid]);
        atomicMin(&g_class_min[tileN + tid], s_clsmin[tid]);
    }
}

// ---------------- fused refine + gather + MSE + active ------------------------
// 1 warp per row: scan bf16 dists, exact fp32 (round-1 op order) on candidates,
// warp-reduce packed (dist,col), then gather codebook row + accumulate MSE.
__global__ __launch_bounds__(256)
void vq_refine_gather(const float* __restrict__ xf, const float* __restrict__ cbf,
                      float* __restrict__ out) {
    const int warp = threadIdx.x >> 5;
    const int lane = threadIdx.x & 31;
    const int row  = blockIdx.x * 8 + warp;

    float s = 0.0f;
    if (row < NR) {
        const float thr = dec_f(g_rowmin_approx[row]) + EPS;
        const uint4* dp = reinterpret_cast<const uint4*>(
            g_dist2 + (size_t)row * (KCB / 2));
        const float4* xr = reinterpret_cast<const float4*>(xf + (size_t)row * DDIM);
        const float xq = g_xsq[row];

        unsigned long long best = 0xFFFFFFFFFFFFFFFFull;
#pragma unroll 4
        for (int j = lane; j < KCB / 8; j += 32) {
            uint4 v = dp[j];
            const uint32_t pk[4] = {v.x, v.y, v.z, v.w};
#pragma unroll
            for (int q = 0; q < 4; q++) {
                float2 f = __bfloat1622float2(
                    *reinterpret_cast<const __nv_bfloat162*>(&pk[q]));
#pragma unroll
                for (int b = 0; b < 2; b++) {
                    float dv = (b == 0) ? f.x : f.y;
                    if (dv <= thr) {
                        const int col = j * 8 + q * 2 + b;
                        const float4* cr =
                            reinterpret_cast<const float4*>(cbf + (size_t)col * DDIM);
                        float dot = 0.0f;     // sequential k-order, one accumulator
#pragma unroll 8
                        for (int k = 0; k < DDIM / 4; k++) {
                            float4 a = xr[k];
                            float4 u = cr[k];
                            dot = fmaf(a.x, u.x, dot);
                            dot = fmaf(a.y, u.y, dot);
                            dot = fmaf(a.z, u.z, dot);
                            dot = fmaf(a.w, u.w, dot);
                        }
                        float dfull = fmaf(-2.0f, dot, xq + g_csq[col]);
                        unsigned long long p =
                            ((unsigned long long)enc_f(dfull) << 32) |
                            (unsigned int)col;
                        if (p < best) best = p;
                    }
                }
            }
        }
#pragma unroll
        for (int o = 16; o; o >>= 1) {
            unsigned long long t = __shfl_xor_sync(0xFFFFFFFFu, best, o);
            if (t < best) best = t;
        }
        const unsigned int tok = (unsigned int)(best & 0xFFFFFFFFull);
        if (lane == 0) g_active[tok] = 1;

        const float4* cp = reinterpret_cast<const float4*>(cbf + (size_t)tok * DDIM);
        float4*       op = reinterpret_cast<float4*>(out + (size_t)row * DDIM);
#pragma unroll
        for (int j2 = lane; j2 < DDIM / 4; j2 += 32) {
            float4 cc = cp[j2];
            float4 v2 = xr[j2];
            op[j2] = cc;
            float dx = cc.x - v2.x, dy = cc.y - v2.y;
            float dz = cc.z - v2.z, dw = cc.w - v2.w;
            s += dx * dx + dy * dy + dz * dz + dw * dw;
        }
    }
#pragma unroll
    for (int o = 16; o; o >>= 1) s += __shfl_xor_sync(0xFFFFFFFFu, s, o);
    __shared__ float ws[8];
    if (lane == 0) ws[warp] = s;
    __syncthreads();
    if (threadIdx.x == 0) {
        float t = 0.0f;
#pragma unroll
        for (int w2 = 0; w2 < 8; w2++) t += ws[w2];
        atomicAdd(&g_mse, t);
    }
}

// ---------------- finalize loss ----------------------------------------------
__global__ void vq_finalize_kernel(float* __restrict__ out, int nd) {
    __shared__ float sh[256];
    float s = 0.0f;
    for (int k = threadIdx.x; k < KCB; k += 256) {
        if (g_active[k] == 0) s += dec_f(g_class_min[k]);
    }
    sh[threadIdx.x] = s;
    __syncthreads();
    for (int o = 128; o; o >>= 1) {
        if (threadIdx.x < o) sh[threadIdx.x] += sh[threadIdx.x + o];
        __syncthreads();
    }
    if (threadIdx.x == 0) {
        float mse = g_mse / (float)((size_t)NR * DDIM);
        float ent = sh[0] / (float)KCB;
        out[nd] = 1.25f * mse + 0.02f * ent;
    }
}

// ---------------- launcher ----------------------------------------------------
extern "C" void kernel_launch(void* const* d_in, const int* in_sizes, int n_in,
                              void* d_out, int out_size) {
    const float* x  = (const float*)d_in[0];
    const float* cb = (const float*)d_in[1];
    float* out = (float*)d_out;

    cudaFuncSetAttribute(vq_gemm,
                         cudaFuncAttributeMaxDynamicSharedMemorySize, SMEM_DYN);

    vq_init_kernel<<<(NR + 255) / 256, 256>>>();
    vq_split_kernel<<<NR / 8, 256>>>(x, NR, 0);
    vq_split_kernel<<<KCB / 8, 256>>>(cb, KCB, 1);

    dim3 grid(KCB / BN, NR / BM);   // (32, 128) = 4096 CTAs
    vq_gemm<<<grid, 512, SMEM_DYN>>>();

    vq_refine_gather<<<NR / 8, 256>>>(x, cb, out);
    vq_finalize_kernel<<<1, 256>>>(out, NR * DDIM);
}

// round 10
// speedup vs baseline: 3.0360x; 1.3167x over previous
#include <cuda_runtime.h>
#include <cuda_bf16.h>
#include <cstdint>

// VectorQuantizer — bf16 HMMA GEMM (emits candidate lists) + fused exact refine/gather.
// inputs:  d_in[0] = inputs  [16,32,32,256] f32  (N=16384 rows, D=256)
//          d_in[1] = codebook [4096,256] f32     (K=4096)
// output:  d_out[0..N*D) = embeddings (straight-through), d_out[N*D] = loss

#define NR    16384
#define KCB   4096
#define DDIM  256
#define BM    128
#define BN    128
#define BK    32
#define NCH   (DDIM / BK)        // 8 k-chunks
#define ROWB  80u                // padded smem row bytes (64 data + 16 pad)
#define ARRB  (128u * ROWB)      // 10240 B per array
#define STGB  (2u * ARRB)        // 20480 B per stage (Ah, Bh)
#define SMEM_DYN (2 * STGB)      // 40960 B
#define EPS   0.15f
#define CAP   128                // candidate slots per row

// ---------------- scratch (__device__ globals) -------------------------------
__device__ __nv_bfloat16 g_Ahi[NR * DDIM];
__device__ __nv_bfloat16 g_Bhi[KCB * DDIM];
__device__ unsigned long long g_cand[(size_t)NR * CAP];  // (f32bits(dred)<<32)|col
__device__ int            g_cand_cnt[NR];
__device__ unsigned int   g_rowmin_approx[NR];       // enc(d_red) global per row
__device__ unsigned int   g_class_min[KCB];
__device__ int            g_active[KCB];
__device__ float          g_mse;
__device__ float          g_xsq[NR];
__device__ float          g_csq[KCB];

// ---------------- helpers ----------------------------------------------------
__device__ __forceinline__ unsigned int enc_f(float f) {
    unsigned int u = __float_as_uint(f);
    return (u & 0x80000000u) ? ~u : (u | 0x80000000u);
}
__device__ __forceinline__ float dec_f(unsigned int e) {
    return (e & 0x80000000u) ? __uint_as_float(e ^ 0x80000000u)
                             : __uint_as_float(~e);
}
__device__ __forceinline__ uint32_t smem_u32(const void* p) {
    uint32_t a;
    asm("{ .reg .u64 t; cvta.to.shared.u64 t, %1; cvt.u32.u64 %0, t; }"
        : "=r"(a) : "l"(p));
    return a;
}
__device__ __forceinline__ void cp16(uint32_t dst, const void* src) {
    asm volatile("cp.async.cg.shared.global [%0], [%1], 16;"
                 :: "r"(dst), "l"(src) : "memory");
}
#define CP_COMMIT() asm volatile("cp.async.commit_group;" ::: "memory")
#define CP_WAIT1()  asm volatile("cp.async.wait_group 1;" ::: "memory")
#define CP_WAIT0()  asm volatile("cp.async.wait_group 0;" ::: "memory")

__device__ __forceinline__ void ldsm4(uint32_t r[4], uint32_t addr) {
    asm volatile("ldmatrix.sync.aligned.m8n8.x4.shared.b16 {%0,%1,%2,%3}, [%4];"
                 : "=r"(r[0]), "=r"(r[1]), "=r"(r[2]), "=r"(r[3]) : "r"(addr));
}
__device__ __forceinline__ uint32_t lds32(uint32_t addr) {
    uint32_t v;
    asm volatile("ld.shared.b32 %0, [%1];" : "=r"(v) : "r"(addr));
    return v;
}
__device__ __forceinline__ void mma_bf16(float c[4], const uint32_t a[4],
                                         uint32_t b0, uint32_t b1) {
    asm volatile(
        "mma.sync.aligned.m16n8k16.row.col.f32.bf16.bf16.f32 "
        "{%0,%1,%2,%3}, {%4,%5,%6,%7}, {%8,%9}, {%0,%1,%2,%3};"
        : "+f"(c[0]), "+f"(c[1]), "+f"(c[2]), "+f"(c[3])
        : "r"(a[0]), "r"(a[1]), "r"(a[2]), "r"(a[3]), "r"(b0), "r"(b1));
}

// ---------------- init --------------------------------------------------------
__global__ void vq_init_kernel() {
    int i = blockIdx.x * blockDim.x + threadIdx.x;
    if (i < NR) { g_rowmin_approx[i] = 0xFFFFFFFFu; g_cand_cnt[i] = 0; }
    if (i < KCB) { g_class_min[i] = 0xFFFFFFFFu; g_active[i] = 0; }
    if (i == 0) g_mse = 0.0f;
}

// ---------------- bf16 convert + squared norms -------------------------------
__global__ void vq_split_kernel(const float* __restrict__ src, int rows, int which) {
    int warp = threadIdx.x >> 5;
    int lane = threadIdx.x & 31;
    int row  = blockIdx.x * 8 + warp;
    if (row >= rows) return;
    __nv_bfloat16* hi = which ? g_Bhi : g_Ahi;
    float*         sq = which ? g_csq : g_xsq;
    const float4* s4 = reinterpret_cast<const float4*>(src + (size_t)row * DDIM);
    __nv_bfloat162* h2 = reinterpret_cast<__nv_bfloat162*>(hi + (size_t)row * DDIM);
    float acc = 0.0f;
#pragma unroll
    for (int j = lane; j < DDIM / 4; j += 32) {
        float4 v = s4[j];
        h2[2 * j]     = __nv_bfloat162(__float2bfloat16_rn(v.x), __float2bfloat16_rn(v.y));
        h2[2 * j + 1] = __nv_bfloat162(__float2bfloat16_rn(v.z), __float2bfloat16_rn(v.w));
        acc += v.x * v.x + v.y * v.y + v.z * v.z + v.w * v.w;
    }
#pragma unroll
    for (int o = 16; o; o >>= 1) acc += __shfl_xor_sync(0xFFFFFFFFu, acc, o);
    if (lane == 0) sq[row] = acc;
}

// ---------------- fused GEMM (single-pass bf16 HMMA, 2-stage, 2 CTA/SM) -------
// CTA: 128x128, 512 threads = 16 warps in 4(M)x4(N); warp tile 32x32.
// Outputs: approx global row-min, per-class full-dist min, candidate lists.
__global__ __launch_bounds__(512, 2)
void vq_gemm() {
    extern __shared__ char dynsm[];
    __shared__ unsigned int s_rowmin[BM];
    __shared__ unsigned int s_clsmin[BN];
    __shared__ float        s_xsq[BM];
    __shared__ float        s_csq[BN];

    const uint32_t sb = smem_u32(dynsm);
    const int tid  = threadIdx.x;
    const int lane = tid & 31;
    const int w    = tid >> 5;
    const int m_base = (w >> 2) * 32;
    const int n_base = (w & 3) * 32;
    const int tileM = blockIdx.y * BM;
    const int tileN = blockIdx.x * BN;

    if (tid < BM) {
        s_rowmin[tid] = 0xFFFFFFFFu;
        s_clsmin[tid] = 0xFFFFFFFFu;
        s_xsq[tid] = g_xsq[tileM + tid];
        s_csq[tid] = g_csq[tileN + tid];
    }

    const __nv_bfloat16* Ah = g_Ahi + (size_t)tileM * DDIM;
    const __nv_bfloat16* Bh = g_Bhi + (size_t)tileN * DDIM;

    float c[2][4][4];
#pragma unroll
    for (int mt = 0; mt < 2; mt++)
#pragma unroll
        for (int nt = 0; nt < 4; nt++)
#pragma unroll
            for (int r = 0; r < 4; r++) c[mt][nt][r] = 0.0f;

    // loader: per stage 2 arrays x 128 rows x 4 chunks(16B) = 1024 cp16 / 512 thr
    const int lrow = tid >> 2;
    const int lch  = tid & 3;
    const uint32_t ldst = (uint32_t)lrow * ROWB + (uint32_t)lch * 16u;
    const size_t lsrc = (size_t)lrow * DDIM + lch * 8;

#define LOAD_CHUNK(stg, k0)                                   \
    do {                                                      \
        uint32_t st_ = sb + (uint32_t)(stg) * STGB;           \
        cp16(st_ + ldst,        Ah + lsrc + (k0));            \
        cp16(st_ + ARRB + ldst, Bh + lsrc + (k0));            \
        CP_COMMIT();                                          \
    } while (0)

    LOAD_CHUNK(0u, 0);

    const uint32_t arow = (uint32_t)(m_base + (lane & 7) + 8 * ((lane >> 3) & 1));
    const uint32_t acol16 = 16u * (uint32_t)(lane >> 4);
    const uint32_t brow = (uint32_t)(n_base + (lane >> 2));
    const uint32_t bcol = 4u * (uint32_t)(lane & 3);

    for (int ch = 0; ch < NCH; ch++) {
        if (ch + 1 < NCH) {
            LOAD_CHUNK((uint32_t)((ch + 1) & 1), (ch + 1) * BK);
            CP_WAIT1();
        } else {
            CP_WAIT0();
        }
        __syncthreads();

        const uint32_t st = sb + (uint32_t)(ch & 1) * STGB;
#pragma unroll
        for (int s16 = 0; s16 < 2; s16++) {
            uint32_t ah[2][4];
#pragma unroll
            for (int mt = 0; mt < 2; mt++) {
                uint32_t ra = (arow + 16u * mt) * ROWB + (uint32_t)(s16 * 32) + acol16;
                ldsm4(ah[mt], st + ra);
            }
#pragma unroll
            for (int nt = 0; nt < 4; nt++) {
                uint32_t rb = (brow + 8u * nt) * ROWB + (uint32_t)(s16 * 32) + bcol;
                uint32_t bh0 = lds32(st + ARRB + rb);
                uint32_t bh1 = lds32(st + ARRB + rb + 16u);
#pragma unroll
                for (int mt = 0; mt < 2; mt++)
                    mma_bf16(c[mt][nt], ah[mt], bh0, bh1);
            }
        }
        __syncthreads();
    }

    // ---- epilogue: tile-local row-min + per-class min ----
    unsigned int cm[4][2];
#pragma unroll
    for (int nt = 0; nt < 4; nt++) { cm[nt][0] = 0xFFFFFFFFu; cm[nt][1] = 0xFFFFFFFFu; }

#pragma unroll
    for (int mt = 0; mt < 2; mt++)
#pragma unroll
        for (int h = 0; h < 2; h++) {
            const int rl = m_base + mt * 16 + (lane >> 2) + 8 * h;
            const float xq = s_xsq[rl];
            unsigned int best = 0xFFFFFFFFu;
#pragma unroll
            for (int nt = 0; nt < 4; nt++) {
                const int cl = n_base + nt * 8 + 2 * (lane & 3);
                float dr0 = fmaf(-2.0f, c[mt][nt][h * 2 + 0], s_csq[cl]);
                float dr1 = fmaf(-2.0f, c[mt][nt][h * 2 + 1], s_csq[cl + 1]);
                unsigned int e0 = enc_f(dr0);
                unsigned int e1 = enc_f(dr1);
                if (e0 < best) best = e0;
                if (e1 < best) best = e1;
                unsigned int f0 = enc_f(dr0 + xq);
                unsigned int f1 = enc_f(dr1 + xq);
                if (f0 < cm[nt][0]) cm[nt][0] = f0;
                if (f1 < cm[nt][1]) cm[nt][1] = f1;
            }
#pragma unroll
            for (int o = 1; o <= 2; o <<= 1) {
                unsigned int t = __shfl_xor_sync(0xFFFFFFFFu, best, o);
                if (t < best) best = t;
            }
            if ((lane & 3) == 0) atomicMin(&s_rowmin[rl], best);
        }

#pragma unroll
    for (int nt = 0; nt < 4; nt++)
#pragma unroll
        for (int b = 0; b < 2; b++) {
            unsigned int v = cm[nt][b];
#pragma unroll
            for (int o = 4; o <= 16; o <<= 1) {
                unsigned int t = __shfl_xor_sync(0xFFFFFFFFu, v, o);
                if (t < v) v = t;
            }
            if (lane < 4) atomicMin(&s_clsmin[n_base + nt * 8 + 2 * lane + b], v);
        }

    __syncthreads();
    if (tid < BM) {
        atomicMin(&g_rowmin_approx[tileM + tid], s_rowmin[tid]);
        atomicMin(&g_class_min[tileN + tid], s_clsmin[tid]);
    }

    // ---- candidate append: dred <= tile_min + EPS (superset of global set) ----
#pragma unroll
    for (int mt = 0; mt < 2; mt++)
#pragma unroll
        for (int h = 0; h < 2; h++) {
            const int rl = m_base + mt * 16 + (lane >> 2) + 8 * h;
            const int row = tileM + rl;
            const float thr = dec_f(s_rowmin[rl]) + EPS;
#pragma unroll
            for (int nt = 0; nt < 4; nt++)
#pragma unroll
                for (int b = 0; b < 2; b++) {
                    const int cl = n_base + nt * 8 + 2 * (lane & 3) + b;
                    float dred = fmaf(-2.0f, c[mt][nt][h * 2 + b], s_csq[cl]);
                    if (dred <= thr) {
                        int idx = atomicAdd(&g_cand_cnt[row], 1);
                        if (idx < CAP)
                            g_cand[(size_t)row * CAP + idx] =
                                ((unsigned long long)__float_as_uint(dred) << 32) |
                                (unsigned int)(tileN + cl);
                    }
                }
        }
}

// ---------------- fused refine + gather + MSE + active ------------------------
// 1 warp per row: filter candidates vs global rowmin+EPS, exact fp32 recompute
// (round-1 op order), warp-reduce packed (dist,col), gather + MSE.
__global__ __launch_bounds__(256)
void vq_refine_gather(const float* __restrict__ xf, const float* __restrict__ cbf,
                      float* __restrict__ out) {
    const int warp = threadIdx.x >> 5;
    const int lane = threadIdx.x & 31;
    const int row  = blockIdx.x * 8 + warp;

    float s = 0.0f;
    if (row < NR) {
        const float thr = dec_f(g_rowmin_approx[row]) + EPS;
        const float4* xr = reinterpret_cast<const float4*>(xf + (size_t)row * DDIM);
        const float xq = g_xsq[row];
        const int cnt = g_cand_cnt[row];

        unsigned long long best = 0xFFFFFFFFFFFFFFFFull;
        if (cnt <= CAP) {
            const unsigned long long* cl = g_cand + (size_t)row * CAP;
            for (int i = lane; i < cnt; i += 32) {
                unsigned long long pc = cl[i];
                float dred = __uint_as_float((unsigned int)(pc >> 32));
                if (dred <= thr) {
                    const int col = (int)(pc & 0xFFFFFFFFull);
                    const float4* cr =
                        reinterpret_cast<const float4*>(cbf + (size_t)col * DDIM);
                    float dot = 0.0f;     // sequential k-order, one accumulator
#pragma unroll 8
                    for (int k = 0; k < DDIM / 4; k++) {
                        float4 a = xr[k];
                        float4 u = cr[k];
                        dot = fmaf(a.x, u.x, dot);
                        dot = fmaf(a.y, u.y, dot);
                        dot = fmaf(a.z, u.z, dot);
                        dot = fmaf(a.w, u.w, dot);
                    }
                    float dfull = fmaf(-2.0f, dot, xq + g_csq[col]);
                    unsigned long long p =
                        ((unsigned long long)enc_f(dfull) << 32) |
                        (unsigned int)col;
                    if (p < best) best = p;
                }
            }
        } else {
            // overflow fallback (deterministic, effectively never taken):
            // full exact scan of the row.
            for (int col = lane; col < KCB; col += 32) {
                const float4* cr =
                    reinterpret_cast<const float4*>(cbf + (size_t)col * DDIM);
                float dot = 0.0f;
#pragma unroll 8
                for (int k = 0; k < DDIM / 4; k++) {
                    float4 a = xr[k];
                    float4 u = cr[k];
                    dot = fmaf(a.x, u.x, dot);
                    dot = fmaf(a.y, u.y, dot);
                    dot = fmaf(a.z, u.z, dot);
                    dot = fmaf(a.w, u.w, dot);
                }
                float dfull = fmaf(-2.0f, dot, xq + g_csq[col]);
                unsigned long long p =
                    ((unsigned long long)enc_f(dfull) << 32) | (unsigned int)col;
                if (p < best) best = p;
            }
        }
#pragma unroll
        for (int o = 16; o; o >>= 1) {
            unsigned long long t = __shfl_xor_sync(0xFFFFFFFFu, best, o);
            if (t < best) best = t;
        }
        const unsigned int tok = (unsigned int)(best & 0xFFFFFFFFull);
        if (lane == 0) g_active[tok] = 1;

        const float4* cp = reinterpret_cast<const float4*>(cbf + (size_t)tok * DDIM);
        float4*       op = reinterpret_cast<float4*>(out + (size_t)row * DDIM);
#pragma unroll
        for (int j2 = lane; j2 < DDIM / 4; j2 += 32) {
            float4 cc = cp[j2];
            float4 v2 = xr[j2];
            op[j2] = cc;
            float dx = cc.x - v2.x, dy = cc.y - v2.y;
            float dz = cc.z - v2.z, dw = cc.w - v2.w;
            s += dx * dx + dy * dy + dz * dz + dw * dw;
        }
    }
#pragma unroll
    for (int o = 16; o; o >>= 1) s += __shfl_xor_sync(0xFFFFFFFFu, s, o);
    __shared__ float ws[8];
    if (lane == 0) ws[warp] = s;
    __syncthreads();
    if (threadIdx.x == 0) {
        float t = 0.0f;
#pragma unroll
        for (int w2 = 0; w2 < 8; w2++) t += ws[w2];
        atomicAdd(&g_mse, t);
    }
}

// ---------------- finalize loss ----------------------------------------------
__global__ void vq_finalize_kernel(float* __restrict__ out, int nd) {
    __shared__ float sh[256];
    float s = 0.0f;
    for (int k = threadIdx.x; k < KCB; k += 256) {
        if (g_active[k] == 0) s += dec_f(g_class_min[k]);
    }
    sh[threadIdx.x] = s;
    __syncthreads();
    for (int o = 128; o; o >>= 1) {
        if (threadIdx.x < o) sh[threadIdx.x] += sh[threadIdx.x + o];
        __syncthreads();
    }
    if (threadIdx.x == 0) {
        float mse = g_mse / (float)((size_t)NR * DDIM);
        float ent = sh[0] / (float)KCB;
        out[nd] = 1.25f * mse + 0.02f * ent;
    }
}

// ---------------- launcher ----------------------------------------------------
extern "C" void kernel_launch(void* const* d_in, const int* in_sizes, int n_in,
                              void* d_out, int out_size) {
    const float* x  = (const float*)d_in[0];
    const float* cb = (const float*)d_in[1];
    float* out = (float*)d_out;

    cudaFuncSetAttribute(vq_gemm,
                         cudaFuncAttributeMaxDynamicSharedMemorySize, SMEM_DYN);

    vq_init_kernel<<<(NR + 255) / 256, 256>>>();
    vq_split_kernel<<<NR / 8, 256>>>(x, NR, 0);
    vq_split_kernel<<<KCB / 8, 256>>>(cb, KCB, 1);

    dim3 grid(KCB / BN, NR / BM);   // (32, 128) = 4096 CTAs
    vq_gemm<<<grid, 512, SMEM_DYN>>>();

    vq_refine_gather<<<NR / 8, 256>>>(x, cb, out);
    vq_finalize_kernel<<<1, 256>>>(out, NR * DDIM);
}

// round 13
// speedup vs baseline: 3.2793x; 1.0801x over previous
#include <cuda_runtime.h>
#include <cuda_bf16.h>
#include <cstdint>

// VectorQuantizer — bf16 HMMA GEMM (candidate lists, ldmatrix B) + fused refine/gather.
// inputs:  d_in[0] = inputs  [16,32,32,256] f32  (N=16384 rows, D=256)
//          d_in[1] = codebook [4096,256] f32     (K=4096)
// output:  d_out[0..N*D) = embeddings (straight-through), d_out[N*D] = loss

#define NR    16384
#define KCB   4096
#define DDIM  256
#define BM    128
#define BN    128
#define BK    32
#define NCH   (DDIM / BK)        // 8 k-chunks
#define ROWB  80u                // padded smem row bytes (64 data + 16 pad)
#define ARRB  (128u * ROWB)      // 10240 B per array
#define STGB  (2u * ARRB)        // 20480 B per stage (Ah, Bh)
#define SMEM_DYN (2 * STGB)      // 40960 B
#define EPS   0.15f
#define CAP   128                // candidate slots per row

// ---------------- scratch (__device__ globals) -------------------------------
__device__ __nv_bfloat16 g_Ahi[NR * DDIM];
__device__ __nv_bfloat16 g_Bhi[KCB * DDIM];
__device__ unsigned long long g_cand[(size_t)NR * CAP];  // (f32bits(dred)<<32)|col
__device__ int            g_cand_cnt[NR];
__device__ unsigned int   g_rowmin_approx[NR];       // enc(d_red) global per row
__device__ unsigned int   g_class_min[KCB];
__device__ int            g_active[KCB];
__device__ float          g_mse;
__device__ float          g_xsq[NR];
__device__ float          g_csq[KCB];

// ---------------- helpers ----------------------------------------------------
__device__ __forceinline__ unsigned int enc_f(float f) {
    unsigned int u = __float_as_uint(f);
    return (u & 0x80000000u) ? ~u : (u | 0x80000000u);
}
__device__ __forceinline__ float dec_f(unsigned int e) {
    return (e & 0x80000000u) ? __uint_as_float(e ^ 0x80000000u)
                             : __uint_as_float(~e);
}
__device__ __forceinline__ uint32_t smem_u32(const void* p) {
    uint32_t a;
    asm("{ .reg .u64 t; cvta.to.shared.u64 t, %1; cvt.u32.u64 %0, t; }"
        : "=r"(a) : "l"(p));
    return a;
}
__device__ __forceinline__ void cp16(uint32_t dst, const void* src) {
    asm volatile("cp.async.cg.shared.global [%0], [%1], 16;"
                 :: "r"(dst), "l"(src) : "memory");
}
#define CP_COMMIT() asm volatile("cp.async.commit_group;" ::: "memory")
#define CP_WAIT1()  asm volatile("cp.async.wait_group 1;" ::: "memory")
#define CP_WAIT0()  asm volatile("cp.async.wait_group 0;" ::: "memory")

__device__ __forceinline__ void ldsm4(uint32_t r[4], uint32_t addr) {
    asm volatile("ldmatrix.sync.aligned.m8n8.x4.shared.b16 {%0,%1,%2,%3}, [%4];"
                 : "=r"(r[0]), "=r"(r[1]), "=r"(r[2]), "=r"(r[3]) : "r"(addr));
}
__device__ __forceinline__ void mma_bf16(float c[4], const uint32_t a[4],
                                         uint32_t b0, uint32_t b1) {
    asm volatile(
        "mma.sync.aligned.m16n8k16.row.col.f32.bf16.bf16.f32 "
        "{%0,%1,%2,%3}, {%4,%5,%6,%7}, {%8,%9}, {%0,%1,%2,%3};"
        : "+f"(c[0]), "+f"(c[1]), "+f"(c[2]), "+f"(c[3])
        : "r"(a[0]), "r"(a[1]), "r"(a[2]), "r"(a[3]), "r"(b0), "r"(b1));
}

// ---------------- init --------------------------------------------------------
__global__ void vq_init_kernel() {
    int i = blockIdx.x * blockDim.x + threadIdx.x;
    if (i < NR) { g_rowmin_approx[i] = 0xFFFFFFFFu; g_cand_cnt[i] = 0; }
    if (i < KCB) { g_class_min[i] = 0xFFFFFFFFu; g_active[i] = 0; }
    if (i == 0) g_mse = 0.0f;
}

// ---------------- bf16 convert + squared norms -------------------------------
__global__ void vq_split_kernel(const float* __restrict__ src, int rows, int which) {
    int warp = threadIdx.x >> 5;
    int lane = threadIdx.x & 31;
    int row  = blockIdx.x * 8 + warp;
    if (row >= rows) return;
    __nv_bfloat16* hi = which ? g_Bhi : g_Ahi;
    float*         sq = which ? g_csq : g_xsq;
    const float4* s4 = reinterpret_cast<const float4*>(src + (size_t)row * DDIM);
    __nv_bfloat162* h2 = reinterpret_cast<__nv_bfloat162*>(hi + (size_t)row * DDIM);
    float acc = 0.0f;
#pragma unroll
    for (int j = lane; j < DDIM / 4; j += 32) {
        float4 v = s4[j];
        h2[2 * j]     = __nv_bfloat162(__float2bfloat16_rn(v.x), __float2bfloat16_rn(v.y));
        h2[2 * j + 1] = __nv_bfloat162(__float2bfloat16_rn(v.z), __float2bfloat16_rn(v.w));
        acc += v.x * v.x + v.y * v.y + v.z * v.z + v.w * v.w;
    }
#pragma unroll
    for (int o = 16; o; o >>= 1) acc += __shfl_xor_sync(0xFFFFFFFFu, acc, o);
    if (lane == 0) sq[row] = acc;
}

// ---------------- fused GEMM (bf16 HMMA, ldmatrix A+B, 2-stage, 2 CTA/SM) -----
// CTA: 128x128, 512 threads = 16 warps in 4(M)x4(N); warp tile 32x32.
__global__ __launch_bounds__(512, 2)
void vq_gemm() {
    extern __shared__ char dynsm[];
    __shared__ unsigned int s_rowmin[BM];
    __shared__ unsigned int s_clsmin[BN];
    __shared__ float        s_xsq[BM];
    __shared__ float        s_csq[BN];

    const uint32_t sb = smem_u32(dynsm);
    const int tid  = threadIdx.x;
    const int lane = tid & 31;
    const int w    = tid >> 5;
    const int m_base = (w >> 2) * 32;
    const int n_base = (w & 3) * 32;
    const int tileM = blockIdx.y * BM;
    const int tileN = blockIdx.x * BN;

    if (tid < BM) {
        s_rowmin[tid] = 0xFFFFFFFFu;
        s_clsmin[tid] = 0xFFFFFFFFu;
        s_xsq[tid] = g_xsq[tileM + tid];
        s_csq[tid] = g_csq[tileN + tid];
    }

    const __nv_bfloat16* Ah = g_Ahi + (size_t)tileM * DDIM;
    const __nv_bfloat16* Bh = g_Bhi + (size_t)tileN * DDIM;

    float c[2][4][4];
#pragma unroll
    for (int mt = 0; mt < 2; mt++)
#pragma unroll
        for (int nt = 0; nt < 4; nt++)
#pragma unroll
            for (int r = 0; r < 4; r++) c[mt][nt][r] = 0.0f;

    // loader: per stage 2 arrays x 128 rows x 4 chunks(16B) = 1024 cp16 / 512 thr
    const int lrow = tid >> 2;
    const int lch  = tid & 3;
    const uint32_t ldst = (uint32_t)lrow * ROWB + (uint32_t)lch * 16u;
    const size_t lsrc = (size_t)lrow * DDIM + lch * 8;

#define LOAD_CHUNK(stg, k0)                                   \
    do {                                                      \
        uint32_t st_ = sb + (uint32_t)(stg) * STGB;           \
        cp16(st_ + ldst,        Ah + lsrc + (k0));            \
        cp16(st_ + ARRB + ldst, Bh + lsrc + (k0));            \
        CP_COMMIT();                                          \
    } while (0)

    LOAD_CHUNK(0u, 0);

    // ldmatrix lane addressing
    const uint32_t arow = (uint32_t)(m_base + (lane & 7) + 8 * ((lane >> 3) & 1));
    const uint32_t acol16 = 16u * (uint32_t)(lane >> 4);
    // B x4: lanes 0-7 -> m0 rows, 8-15 -> m1, 16-23 -> m2, 24-31 -> m3
    // m0=(n+0..7, k lo), m1=(n+0..7, k hi), m2=(n+8..15, k lo), m3=(n+8..15, k hi)
    const uint32_t brow2 = (uint32_t)(n_base + ((lane >> 4) & 1) * 8 + (lane & 7));
    const uint32_t bcol2 = 16u * (uint32_t)((lane >> 3) & 1);

    for (int ch = 0; ch < NCH; ch++) {
        if (ch + 1 < NCH) {
            LOAD_CHUNK((uint32_t)((ch + 1) & 1), (ch + 1) * BK);
            CP_WAIT1();
        } else {
            CP_WAIT0();
        }
        __syncthreads();

        const uint32_t st = sb + (uint32_t)(ch & 1) * STGB;
#pragma unroll
        for (int s16 = 0; s16 < 2; s16++) {
            uint32_t ah[2][4];
#pragma unroll
            for (int mt = 0; mt < 2; mt++) {
                uint32_t ra = (arow + 16u * mt) * ROWB + (uint32_t)(s16 * 32) + acol16;
                ldsm4(ah[mt], st + ra);
            }
            uint32_t bq[2][4];    // [pair p][m0..m3]; p=0 -> nt 0,1; p=1 -> nt 2,3
#pragma unroll
            for (int p = 0; p < 2; p++) {
                uint32_t rb = (brow2 + 16u * p) * ROWB + (uint32_t)(s16 * 32) + bcol2;
                ldsm4(bq[p], st + ARRB + rb);
            }
#pragma unroll
            for (int nt = 0; nt < 4; nt++) {
                uint32_t b0 = bq[nt >> 1][(nt & 1) * 2 + 0];
                uint32_t b1 = bq[nt >> 1][(nt & 1) * 2 + 1];
#pragma unroll
                for (int mt = 0; mt < 2; mt++)
                    mma_bf16(c[mt][nt], ah[mt], b0, b1);
            }
        }
        __syncthreads();
    }

    // ---- epilogue: tile-local row-min + per-class min ----
    unsigned int cm[4][2];
#pragma unroll
    for (int nt = 0; nt < 4; nt++) { cm[nt][0] = 0xFFFFFFFFu; cm[nt][1] = 0xFFFFFFFFu; }

#pragma unroll
    for (int mt = 0; mt < 2; mt++)
#pragma unroll
        for (int h = 0; h < 2; h++) {
            const int rl = m_base + mt * 16 + (lane >> 2) + 8 * h;
            const float xq = s_xsq[rl];
            unsigned int best = 0xFFFFFFFFu;
#pragma unroll
            for (int nt = 0; nt < 4; nt++) {
                const int cl = n_base + nt * 8 + 2 * (lane & 3);
                float dr0 = fmaf(-2.0f, c[mt][nt][h * 2 + 0], s_csq[cl]);
                float dr1 = fmaf(-2.0f, c[mt][nt][h * 2 + 1], s_csq[cl + 1]);
                unsigned int e0 = enc_f(dr0);
                unsigned int e1 = enc_f(dr1);
                if (e0 < best) best = e0;
                if (e1 < best) best = e1;
                unsigned int f0 = enc_f(dr0 + xq);
                unsigned int f1 = enc_f(dr1 + xq);
                if (f0 < cm[nt][0]) cm[nt][0] = f0;
                if (f1 < cm[nt][1]) cm[nt][1] = f1;
            }
#pragma unroll
            for (int o = 1; o <= 2; o <<= 1) {
                unsigned int t = __shfl_xor_sync(0xFFFFFFFFu, best, o);
                if (t < best) best = t;
            }
            if ((lane & 3) == 0) atomicMin(&s_rowmin[rl], best);
        }

#pragma unroll
    for (int nt = 0; nt < 4; nt++)
#pragma unroll
        for (int b = 0; b < 2; b++) {
            unsigned int v = cm[nt][b];
#pragma unroll
            for (int o = 4; o <= 16; o <<= 1) {
                unsigned int t = __shfl_xor_sync(0xFFFFFFFFu, v, o);
                if (t < v) v = t;
            }
            if (lane < 4) atomicMin(&s_clsmin[n_base + nt * 8 + 2 * lane + b], v);
        }

    __syncthreads();
    if (tid < BM) {
        atomicMin(&g_rowmin_approx[tileM + tid], s_rowmin[tid]);
        atomicMin(&g_class_min[tileN + tid], s_clsmin[tid]);
    }

    // ---- candidate append: dred <= tile_min + EPS, quad-aggregated atomics ----
    // All __shfl_sync collectives are executed UNCONDITIONALLY by every lane
    // (the round-12 crash was a full-mask shuffle inside a quad-divergent branch).
#pragma unroll
    for (int mt = 0; mt < 2; mt++)
#pragma unroll
        for (int h = 0; h < 2; h++) {
            const int rl = m_base + mt * 16 + (lane >> 2) + 8 * h;
            const int row = tileM + rl;
            const float thr = dec_f(s_rowmin[rl]) + EPS;
            unsigned int mask = 0;
#pragma unroll
            for (int nt = 0; nt < 4; nt++)
#pragma unroll
                for (int b = 0; b < 2; b++) {
                    const int cl = n_base + nt * 8 + 2 * (lane & 3) + b;
                    float dred = fmaf(-2.0f, c[mt][nt][h * 2 + b], s_csq[cl]);
                    if (dred <= thr) mask |= 1u << (nt * 2 + b);
                }
            int cnt = __popc(mask);
            // inclusive quad-scan of counts (unconditional collectives)
            int incl = cnt, t;
            t = __shfl_up_sync(0xFFFFFFFFu, incl, 1, 4); if ((lane & 3) >= 1) incl += t;
            t = __shfl_up_sync(0xFFFFFFFFu, incl, 2, 4); if ((lane & 3) >= 2) incl += t;
            int total = __shfl_sync(0xFFFFFFFFu, incl, 3, 4);
            int base = 0;
            if ((lane & 3) == 0 && total > 0)
                base = atomicAdd(&g_cand_cnt[row], total);
            base = __shfl_sync(0xFFFFFFFFu, base, 0, 4);   // unconditional
            int slot = base + (incl - cnt);
            if (mask) {
#pragma unroll
                for (int nt = 0; nt < 4; nt++)
#pragma unroll
                    for (int b = 0; b < 2; b++) {
                        if (mask & (1u << (nt * 2 + b))) {
                            const int cl = n_base + nt * 8 + 2 * (lane & 3) + b;
                            float dred = fmaf(-2.0f, c[mt][nt][h * 2 + b],
                                              s_csq[cl]);
                            if (slot < CAP)
                                g_cand[(size_t)row * CAP + slot] =
                                    ((unsigned long long)__float_as_uint(dred)
                                         << 32) |
                                    (unsigned int)(tileN + cl);
                            slot++;
                        }
                    }
            }
        }
}

// ---------------- fused refine + gather + MSE + active ------------------------
// 1 warp per row: filter candidates vs global rowmin+EPS, exact fp32 recompute
// (round-1 op order), warp-reduce packed (dist,col), gather + MSE.
__global__ __launch_bounds__(256)
void vq_refine_gather(const float* __restrict__ xf, const float* __restrict__ cbf,
                      float* __restrict__ out) {
    const int warp = threadIdx.x >> 5;
    const int lane = threadIdx.x & 31;
    const int row  = blockIdx.x * 8 + warp;

    float s = 0.0f;
    if (row < NR) {
        const float thr = dec_f(g_rowmin_approx[row]) + EPS;
        const float4* xr = reinterpret_cast<const float4*>(xf + (size_t)row * DDIM);
        const float xq = g_xsq[row];
        const int cnt = g_cand_cnt[row];

        unsigned long long best = 0xFFFFFFFFFFFFFFFFull;
        if (cnt <= CAP) {
            const unsigned long long* cl = g_cand + (size_t)row * CAP;
            for (int i = lane; i < cnt; i += 32) {
                unsigned long long pc = cl[i];
                float dred = __uint_as_float((unsigned int)(pc >> 32));
                if (dred <= thr) {
                    const int col = (int)(pc & 0xFFFFFFFFull);
                    const float4* cr =
                        reinterpret_cast<const float4*>(cbf + (size_t)col * DDIM);
                    float dot = 0.0f;     // sequential k-order, one accumulator
#pragma unroll 8
                    for (int k = 0; k < DDIM / 4; k++) {
                        float4 a = xr[k];
                        float4 u = cr[k];
                        dot = fmaf(a.x, u.x, dot);
                        dot = fmaf(a.y, u.y, dot);
                        dot = fmaf(a.z, u.z, dot);
                        dot = fmaf(a.w, u.w, dot);
                    }
                    float dfull = fmaf(-2.0f, dot, xq + g_csq[col]);
                    unsigned long long p =
                        ((unsigned long long)enc_f(dfull) << 32) |
                        (unsigned int)col;
                    if (p < best) best = p;
                }
            }
        } else {
            // overflow fallback (deterministic): full exact scan of the row.
            for (int col = lane; col < KCB; col += 32) {
                const float4* cr =
                    reinterpret_cast<const float4*>(cbf + (size_t)col * DDIM);
                float dot = 0.0f;
#pragma unroll 8
                for (int k = 0; k < DDIM / 4; k++) {
                    float4 a = xr[k];
                    float4 u = cr[k];
                    dot = fmaf(a.x, u.x, dot);
                    dot = fmaf(a.y, u.y, dot);
                    dot = fmaf(a.z, u.z, dot);
                    dot = fmaf(a.w, u.w, dot);
                }
                float dfull = fmaf(-2.0f, dot, xq + g_csq[col]);
                unsigned long long p =
                    ((unsigned long long)enc_f(dfull) << 32) | (unsigned int)col;
                if (p < best) best = p;
            }
        }
#pragma unroll
        for (int o = 16; o; o >>= 1) {
            unsigned long long t = __shfl_xor_sync(0xFFFFFFFFu, best, o);
            if (t < best) best = t;
        }
        const unsigned int tok = (unsigned int)(best & 0xFFFFFFFFull);
        if (lane == 0) g_active[tok] = 1;

        const float4* cp = reinterpret_cast<const float4*>(cbf + (size_t)tok * DDIM);
        float4*       op = reinterpret_cast<float4*>(out + (size_t)row * DDIM);
#pragma unroll
        for (int j2 = lane; j2 < DDIM / 4; j2 += 32) {
            float4 cc = cp[j2];
            float4 v2 = xr[j2];
            op[j2] = cc;
            float dx = cc.x - v2.x, dy = cc.y - v2.y;
            float dz = cc.z - v2.z, dw = cc.w - v2.w;
            s += dx * dx + dy * dy + dz * dz + dw * dw;
        }
    }
#pragma unroll
    for (int o = 16; o; o >>= 1) s += __shfl_xor_sync(0xFFFFFFFFu, s, o);
    __shared__ float ws[8];
    if (lane == 0) ws[warp] = s;
    __syncthreads();
    if (threadIdx.x == 0) {
        float t = 0.0f;
#pragma unroll
        for (int w2 = 0; w2 < 8; w2++) t += ws[w2];
        atomicAdd(&g_mse, t);
    }
}

// ---------------- finalize loss ----------------------------------------------
__global__ void vq_finalize_kernel(float* __restrict__ out, int nd) {
    __shared__ float sh[256];
    float s = 0.0f;
    for (int k = threadIdx.x; k < KCB; k += 256) {
        if (g_active[k] == 0) s += dec_f(g_class_min[k]);
    }
    sh[threadIdx.x] = s;
    __syncthreads();
    for (int o = 128; o; o >>= 1) {
        if (threadIdx.x < o) sh[threadIdx.x] += sh[threadIdx.x + o];
        __syncthreads();
    }
    if (threadIdx.x == 0) {
        float mse = g_mse / (float)((size_t)NR * DDIM);
        float ent = sh[0] / (float)KCB;
        out[nd] = 1.25f * mse + 0.02f * ent;
    }
}

// ---------------- launcher ----------------------------------------------------
extern "C" void kernel_launch(void* const* d_in, const int* in_sizes, int n_in,
                              void* d_out, int out_size) {
    const float* x  = (const float*)d_in[0];
    const float* cb = (const float*)d_in[1];
    float* out = (float*)d_out;

    cudaFuncSetAttribute(vq_gemm,
                         cudaFuncAttributeMaxDynamicSharedMemorySize, SMEM_DYN);

    vq_init_kernel<<<(NR + 255) / 256, 256>>>();
    vq_split_kernel<<<NR / 8, 256>>>(x, NR, 0);
    vq_split_kernel<<<KCB / 8, 256>>>(cb, KCB, 1);

    dim3 grid(KCB / BN, NR / BM);   // (32, 128) = 4096 CTAs
    vq_gemm<<<grid, 512, SMEM_DYN>>>();

    vq_refine_gather<<<NR / 8, 256>>>(x, cb, out);
    vq_finalize_kernel<<<1, 256>>>(out, NR * DDIM);
}

// round 14
// speedup vs baseline: 3.4402x; 1.0491x over previous
#include <cuda_runtime.h>
#include <cuda_bf16.h>
#include <cstdint>

// VectorQuantizer — bf16 HMMA GEMM (3-stage pipeline, 1 sync/chunk) + refine/gather.
// inputs:  d_in[0] = inputs  [16,32,32,256] f32  (N=16384 rows, D=256)
//          d_in[1] = codebook [4096,256] f32     (K=4096)
// output:  d_out[0..N*D) = embeddings (straight-through), d_out[N*D] = loss

#define NR    16384
#define KCB   4096
#define DDIM  256
#define BM    128
#define BN    128
#define BK    32
#define NCH   (DDIM / BK)        // 8 k-chunks
#define ROWB  80u                // padded smem row bytes (64 data + 16 pad)
#define ARRB  (128u * ROWB)      // 10240 B per array
#define STGB  (2u * ARRB)        // 20480 B per stage (Ah, Bh)
#define NSTG  3
#define SMEM_DYN (NSTG * STGB)   // 61440 B
#define EPS   0.15f
#define CAP   128                // candidate slots per row

// ---------------- scratch (__device__ globals) -------------------------------
__device__ __nv_bfloat16 g_Ahi[NR * DDIM];
__device__ __nv_bfloat16 g_Bhi[KCB * DDIM];
__device__ unsigned long long g_cand[(size_t)NR * CAP];  // (f32bits(dred)<<32)|col
__device__ int            g_cand_cnt[NR];
__device__ unsigned int   g_rowmin_approx[NR];       // enc(d_red) global per row
__device__ unsigned int   g_class_min[KCB];
__device__ int            g_active[KCB];
__device__ float          g_mse;
__device__ float          g_xsq[NR];
__device__ float          g_csq[KCB];

// ---------------- helpers ----------------------------------------------------
__device__ __forceinline__ unsigned int enc_f(float f) {
    unsigned int u = __float_as_uint(f);
    return (u & 0x80000000u) ? ~u : (u | 0x80000000u);
}
__device__ __forceinline__ float dec_f(unsigned int e) {
    return (e & 0x80000000u) ? __uint_as_float(e ^ 0x80000000u)
                             : __uint_as_float(~e);
}
__device__ __forceinline__ uint32_t smem_u32(const void* p) {
    uint32_t a;
    asm("{ .reg .u64 t; cvta.to.shared.u64 t, %1; cvt.u32.u64 %0, t; }"
        : "=r"(a) : "l"(p));
    return a;
}
__device__ __forceinline__ void cp16(uint32_t dst, const void* src) {
    asm volatile("cp.async.cg.shared.global [%0], [%1], 16;"
                 :: "r"(dst), "l"(src) : "memory");
}
#define CP_COMMIT() asm volatile("cp.async.commit_group;" ::: "memory")
#define CP_WAIT1()  asm volatile("cp.async.wait_group 1;" ::: "memory")
#define CP_WAIT0()  asm volatile("cp.async.wait_group 0;" ::: "memory")

__device__ __forceinline__ void ldsm4(uint32_t r[4], uint32_t addr) {
    asm volatile("ldmatrix.sync.aligned.m8n8.x4.shared.b16 {%0,%1,%2,%3}, [%4];"
                 : "=r"(r[0]), "=r"(r[1]), "=r"(r[2]), "=r"(r[3]) : "r"(addr));
}
__device__ __forceinline__ void mma_bf16(float c[4], const uint32_t a[4],
                                         uint32_t b0, uint32_t b1) {
    asm volatile(
        "mma.sync.aligned.m16n8k16.row.col.f32.bf16.bf16.f32 "
        "{%0,%1,%2,%3}, {%4,%5,%6,%7}, {%8,%9}, {%0,%1,%2,%3};"
        : "+f"(c[0]), "+f"(c[1]), "+f"(c[2]), "+f"(c[3])
        : "r"(a[0]), "r"(a[1]), "r"(a[2]), "r"(a[3]), "r"(b0), "r"(b1));
}

// ---------------- init --------------------------------------------------------
__global__ void vq_init_kernel() {
    int i = blockIdx.x * blockDim.x + threadIdx.x;
    if (i < NR) { g_rowmin_approx[i] = 0xFFFFFFFFu; g_cand_cnt[i] = 0; }
    if (i < KCB) { g_class_min[i] = 0xFFFFFFFFu; g_active[i] = 0; }
    if (i == 0) g_mse = 0.0f;
}

// ---------------- bf16 convert + squared norms -------------------------------
__global__ void vq_split_kernel(const float* __restrict__ src, int rows, int which) {
    int warp = threadIdx.x >> 5;
    int lane = threadIdx.x & 31;
    int row  = blockIdx.x * 8 + warp;
    if (row >= rows) return;
    __nv_bfloat16* hi = which ? g_Bhi : g_Ahi;
    float*         sq = which ? g_csq : g_xsq;
    const float4* s4 = reinterpret_cast<const float4*>(src + (size_t)row * DDIM);
    __nv_bfloat162* h2 = reinterpret_cast<__nv_bfloat162*>(hi + (size_t)row * DDIM);
    float acc = 0.0f;
#pragma unroll
    for (int j = lane; j < DDIM / 4; j += 32) {
        float4 v = s4[j];
        h2[2 * j]     = __nv_bfloat162(__float2bfloat16_rn(v.x), __float2bfloat16_rn(v.y));
        h2[2 * j + 1] = __nv_bfloat162(__float2bfloat16_rn(v.z), __float2bfloat16_rn(v.w));
        acc += v.x * v.x + v.y * v.y + v.z * v.z + v.w * v.w;
    }
#pragma unroll
    for (int o = 16; o; o >>= 1) acc += __shfl_xor_sync(0xFFFFFFFFu, acc, o);
    if (lane == 0) sq[row] = acc;
}

// ---------------- fused GEMM (bf16 HMMA, 3-stage, 1 sync/chunk, 2 CTA/SM) -----
// CTA: 128x128, 512 threads = 16 warps in 4(M)x4(N); warp tile 32x32.
// Pipeline: prologue loads chunks 0,1. Per chunk: WAIT -> sync -> compute
//           -> LOAD(ch+2). Write-target stage (ch+2)%3 == (ch-1)%3 was last
//           read in chunk ch-1; sync(ch) guarantees all warps finished it.
__global__ __launch_bounds__(512, 2)
void vq_gemm() {
    extern __shared__ char dynsm[];
    __shared__ unsigned int s_rowmin[BM];
    __shared__ unsigned int s_clsmin[BN];
    __shared__ float        s_xsq[BM];
    __shared__ float        s_csq[BN];

    const uint32_t sb = smem_u32(dynsm);
    const int tid  = threadIdx.x;
    const int lane = tid & 31;
    const int w    = tid >> 5;
    const int m_base = (w >> 2) * 32;
    const int n_base = (w & 3) * 32;
    const int tileM = blockIdx.y * BM;
    const int tileN = blockIdx.x * BN;

    if (tid < BM) {
        s_rowmin[tid] = 0xFFFFFFFFu;
        s_clsmin[tid] = 0xFFFFFFFFu;
        s_xsq[tid] = g_xsq[tileM + tid];
        s_csq[tid] = g_csq[tileN + tid];
    }

    const __nv_bfloat16* Ah = g_Ahi + (size_t)tileM * DDIM;
    const __nv_bfloat16* Bh = g_Bhi + (size_t)tileN * DDIM;

    float c[2][4][4];
#pragma unroll
    for (int mt = 0; mt < 2; mt++)
#pragma unroll
        for (int nt = 0; nt < 4; nt++)
#pragma unroll
            for (int r = 0; r < 4; r++) c[mt][nt][r] = 0.0f;

    // loader: per stage 2 arrays x 128 rows x 4 chunks(16B) = 1024 cp16 / 512 thr
    const int lrow = tid >> 2;
    const int lch  = tid & 3;
    const uint32_t ldst = (uint32_t)lrow * ROWB + (uint32_t)lch * 16u;
    const size_t lsrc = (size_t)lrow * DDIM + lch * 8;

#define LOAD_CHUNK(stg, k0)                                   \
    do {                                                      \
        uint32_t st_ = sb + (uint32_t)(stg) * STGB;           \
        cp16(st_ + ldst,        Ah + lsrc + (k0));            \
        cp16(st_ + ARRB + ldst, Bh + lsrc + (k0));            \
        CP_COMMIT();                                          \
    } while (0)

    LOAD_CHUNK(0, 0);
    LOAD_CHUNK(1, BK);

    // ldmatrix lane addressing
    const uint32_t arow = (uint32_t)(m_base + (lane & 7) + 8 * ((lane >> 3) & 1));
    const uint32_t acol16 = 16u * (uint32_t)(lane >> 4);
    const uint32_t brow2 = (uint32_t)(n_base + ((lane >> 4) & 1) * 8 + (lane & 7));
    const uint32_t bcol2 = 16u * (uint32_t)((lane >> 3) & 1);

#pragma unroll
    for (int ch = 0; ch < NCH; ch++) {
        if (ch < NCH - 1) { CP_WAIT1(); } else { CP_WAIT0(); }
        __syncthreads();

        const uint32_t st = sb + (uint32_t)(ch % NSTG) * STGB;
#pragma unroll
        for (int s16 = 0; s16 < 2; s16++) {
            uint32_t ah[2][4];
#pragma unroll
            for (int mt = 0; mt < 2; mt++) {
                uint32_t ra = (arow + 16u * mt) * ROWB + (uint32_t)(s16 * 32) + acol16;
                ldsm4(ah[mt], st + ra);
            }
            uint32_t bq[2][4];    // [pair p][m0..m3]; p=0 -> nt 0,1; p=1 -> nt 2,3
#pragma unroll
            for (int p = 0; p < 2; p++) {
                uint32_t rb = (brow2 + 16u * p) * ROWB + (uint32_t)(s16 * 32) + bcol2;
                ldsm4(bq[p], st + ARRB + rb);
            }
#pragma unroll
            for (int nt = 0; nt < 4; nt++) {
                uint32_t b0 = bq[nt >> 1][(nt & 1) * 2 + 0];
                uint32_t b1 = bq[nt >> 1][(nt & 1) * 2 + 1];
#pragma unroll
                for (int mt = 0; mt < 2; mt++)
                    mma_bf16(c[mt][nt], ah[mt], b0, b1);
            }
        }
        if (ch + 2 < NCH) LOAD_CHUNK((ch + 2) % NSTG, (ch + 2) * BK);
    }

    // ---- epilogue: tile-local row-min + per-class min ----
    unsigned int cm[4][2];
#pragma unroll
    for (int nt = 0; nt < 4; nt++) { cm[nt][0] = 0xFFFFFFFFu; cm[nt][1] = 0xFFFFFFFFu; }

#pragma unroll
    for (int mt = 0; mt < 2; mt++)
#pragma unroll
        for (int h = 0; h < 2; h++) {
            const int rl = m_base + mt * 16 + (lane >> 2) + 8 * h;
            const float xq = s_xsq[rl];
            unsigned int best = 0xFFFFFFFFu;
#pragma unroll
            for (int nt = 0; nt < 4; nt++) {
                const int cl = n_base + nt * 8 + 2 * (lane & 3);
                float dr0 = fmaf(-2.0f, c[mt][nt][h * 2 + 0], s_csq[cl]);
                float dr1 = fmaf(-2.0f, c[mt][nt][h * 2 + 1], s_csq[cl + 1]);
                unsigned int e0 = enc_f(dr0);
                unsigned int e1 = enc_f(dr1);
                if (e0 < best) best = e0;
                if (e1 < best) best = e1;
                unsigned int f0 = enc_f(dr0 + xq);
                unsigned int f1 = enc_f(dr1 + xq);
                if (f0 < cm[nt][0]) cm[nt][0] = f0;
                if (f1 < cm[nt][1]) cm[nt][1] = f1;
            }
#pragma unroll
            for (int o = 1; o <= 2; o <<= 1) {
                unsigned int t = __shfl_xor_sync(0xFFFFFFFFu, best, o);
                if (t < best) best = t;
            }
            if ((lane & 3) == 0) atomicMin(&s_rowmin[rl], best);
        }

#pragma unroll
    for (int nt = 0; nt < 4; nt++)
#pragma unroll
        for (int b = 0; b < 2; b++) {
            unsigned int v = cm[nt][b];
#pragma unroll
            for (int o = 4; o <= 16; o <<= 1) {
                unsigned int t = __shfl_xor_sync(0xFFFFFFFFu, v, o);
                if (t < v) v = t;
            }
            if (lane < 4) atomicMin(&s_clsmin[n_base + nt * 8 + 2 * lane + b], v);
        }

    __syncthreads();
    if (tid < BM) {
        atomicMin(&g_rowmin_approx[tileM + tid], s_rowmin[tid]);
        atomicMin(&g_class_min[tileN + tid], s_clsmin[tid]);
    }

    // ---- candidate append: dred <= tile_min + EPS, quad-aggregated atomics ----
    // All __shfl_sync collectives execute unconditionally on every lane.
#pragma unroll
    for (int mt = 0; mt < 2; mt++)
#pragma unroll
        for (int h = 0; h < 2; h++) {
            const int rl = m_base + mt * 16 + (lane >> 2) + 8 * h;
            const int row = tileM + rl;
            const float thr = dec_f(s_rowmin[rl]) + EPS;
            unsigned int mask = 0;
#pragma unroll
            for (int nt = 0; nt < 4; nt++)
#pragma unroll
                for (int b = 0; b < 2; b++) {
                    const int cl = n_base + nt * 8 + 2 * (lane & 3) + b;
                    float dred = fmaf(-2.0f, c[mt][nt][h * 2 + b], s_csq[cl]);
                    if (dred <= thr) mask |= 1u << (nt * 2 + b);
                }
            int cnt = __popc(mask);
            int incl = cnt, t;
            t = __shfl_up_sync(0xFFFFFFFFu, incl, 1, 4); if ((lane & 3) >= 1) incl += t;
            t = __shfl_up_sync(0xFFFFFFFFu, incl, 2, 4); if ((lane & 3) >= 2) incl += t;
            int total = __shfl_sync(0xFFFFFFFFu, incl, 3, 4);
            int base = 0;
            if ((lane & 3) == 0 && total > 0)
                base = atomicAdd(&g_cand_cnt[row], total);
            base = __shfl_sync(0xFFFFFFFFu, base, 0, 4);   // unconditional
            int slot = base + (incl - cnt);
            if (mask) {
#pragma unroll
                for (int nt = 0; nt < 4; nt++)
#pragma unroll
                    for (int b = 0; b < 2; b++) {
                        if (mask & (1u << (nt * 2 + b))) {
                            const int cl = n_base + nt * 8 + 2 * (lane & 3) + b;
                            float dred = fmaf(-2.0f, c[mt][nt][h * 2 + b],
                                              s_csq[cl]);
                            if (slot < CAP)
                                g_cand[(size_t)row * CAP + slot] =
                                    ((unsigned long long)__float_as_uint(dred)
                                         << 32) |
                                    (unsigned int)(tileN + cl);
                            slot++;
                        }
                    }
            }
        }
}

// ---------------- fused refine + gather + MSE + active ------------------------
__global__ __launch_bounds__(256)
void vq_refine_gather(const float* __restrict__ xf, const float* __restrict__ cbf,
                      float* __restrict__ out) {
    const int warp = threadIdx.x >> 5;
    const int lane = threadIdx.x & 31;
    const int row  = blockIdx.x * 8 + warp;

    float s = 0.0f;
    if (row < NR) {
        const float thr = dec_f(g_rowmin_approx[row]) + EPS;
        const float4* xr = reinterpret_cast<const float4*>(xf + (size_t)row * DDIM);
        const float xq = g_xsq[row];
        const int cnt = g_cand_cnt[row];

        unsigned long long best = 0xFFFFFFFFFFFFFFFFull;
        if (cnt <= CAP) {
            const unsigned long long* cl = g_cand + (size_t)row * CAP;
            for (int i = lane; i < cnt; i += 32) {
                unsigned long long pc = cl[i];
                float dred = __uint_as_float((unsigned int)(pc >> 32));
                if (dred <= thr) {
                    const int col = (int)(pc & 0xFFFFFFFFull);
                    const float4* cr =
                        reinterpret_cast<const float4*>(cbf + (size_t)col * DDIM);
                    float dot = 0.0f;     // sequential k-order, one accumulator
#pragma unroll 8
                    for (int k = 0; k < DDIM / 4; k++) {
                        float4 a = xr[k];
                        float4 u = cr[k];
                        dot = fmaf(a.x, u.x, dot);
                        dot = fmaf(a.y, u.y, dot);
                        dot = fmaf(a.z, u.z, dot);
                        dot = fmaf(a.w, u.w, dot);
                    }
                    float dfull = fmaf(-2.0f, dot, xq + g_csq[col]);
                    unsigned long long p =
                        ((unsigned long long)enc_f(dfull) << 32) |
                        (unsigned int)col;
                    if (p < best) best = p;
                }
            }
        } else {
            // overflow fallback (deterministic): full exact scan of the row.
            for (int col = lane; col < KCB; col += 32) {
                const float4* cr =
                    reinterpret_cast<const float4*>(cbf + (size_t)col * DDIM);
                float dot = 0.0f;
#pragma unroll 8
                for (int k = 0; k < DDIM / 4; k++) {
                    float4 a = xr[k];
                    float4 u = cr[k];
                    dot = fmaf(a.x, u.x, dot);
                    dot = fmaf(a.y, u.y, dot);
                    dot = fmaf(a.z, u.z, dot);
                    dot = fmaf(a.w, u.w, dot);
                }
                float dfull = fmaf(-2.0f, dot, xq + g_csq[col]);
                unsigned long long p =
                    ((unsigned long long)enc_f(dfull) << 32) | (unsigned int)col;
                if (p < best) best = p;
            }
        }
#pragma unroll
        for (int o = 16; o; o >>= 1) {
            unsigned long long t = __shfl_xor_sync(0xFFFFFFFFu, best, o);
            if (t < best) best = t;
        }
        const unsigned int tok = (unsigned int)(best & 0xFFFFFFFFull);
        if (lane == 0) g_active[tok] = 1;

        const float4* cp = reinterpret_cast<const float4*>(cbf + (size_t)tok * DDIM);
        float4*       op = reinterpret_cast<float4*>(out + (size_t)row * DDIM);
#pragma unroll
        for (int j2 = lane; j2 < DDIM / 4; j2 += 32) {
            float4 cc = cp[j2];
            float4 v2 = xr[j2];
            op[j2] = cc;
            float dx = cc.x - v2.x, dy = cc.y - v2.y;
            float dz = cc.z - v2.z, dw = cc.w - v2.w;
            s += dx * dx + dy * dy + dz * dz + dw * dw;
        }
    }
#pragma unroll
    for (int o = 16; o; o >>= 1) s += __shfl_xor_sync(0xFFFFFFFFu, s, o);
    __shared__ float ws[8];
    if (lane == 0) ws[warp] = s;
    __syncthreads();
    if (threadIdx.x == 0) {
        float t = 0.0f;
#pragma unroll
        for (int w2 = 0; w2 < 8; w2++) t += ws[w2];
        atomicAdd(&g_mse, t);
    }
}

// ---------------- finalize loss ----------------------------------------------
__global__ void vq_finalize_kernel(float* __restrict__ out, int nd) {
    __shared__ float sh[256];
    float s = 0.0f;
    for (int k = threadIdx.x; k < KCB; k += 256) {
        if (g_active[k] == 0) s += dec_f(g_class_min[k]);
    }
    sh[threadIdx.x] = s;
    __syncthreads();
    for (int o = 128; o; o >>= 1) {
        if (threadIdx.x < o) sh[threadIdx.x] += sh[threadIdx.x + o];
        __syncthreads();
    }
    if (threadIdx.x == 0) {
        float mse = g_mse / (float)((size_t)NR * DDIM);
        float ent = sh[0] / (float)KCB;
        out[nd] = 1.25f * mse + 0.02f * ent;
    }
}

// ---------------- launcher ----------------------------------------------------
extern "C" void kernel_launch(void* const* d_in, const int* in_sizes, int n_in,
                              void* d_out, int out_size) {
    const float* x  = (const float*)d_in[0];
    const float* cb = (const float*)d_in[1];
    float* out = (float*)d_out;

    cudaFuncSetAttribute(vq_gemm,
                         cudaFuncAttributeMaxDynamicSharedMemorySize, SMEM_DYN);

    vq_init_kernel<<<(NR + 255) / 256, 256>>>();
    vq_split_kernel<<<NR / 8, 256>>>(x, NR, 0);
    vq_split_kernel<<<KCB / 8, 256>>>(cb, KCB, 1);

    dim3 grid(KCB / BN, NR / BM);   // (32, 128) = 4096 CTAs
    vq_gemm<<<grid, 512, SMEM_DYN>>>();

    vq_refine_gather<<<NR / 8, 256>>>(x, cb, out);
    vq_finalize_kernel<<<1, 256>>>(out, NR * DDIM);
}

// round 15
// speedup vs baseline: 3.5150x; 1.0217x over previous
#include <cuda_runtime.h>
#include <cuda_bf16.h>
#include <cstdint>

// VectorQuantizer — bf16 HMMA GEMM (BK=64, 2-stage, 1 sync/chunk) + refine/gather.
// inputs:  d_in[0] = inputs  [16,32,32,256] f32  (N=16384 rows, D=256)
//          d_in[1] = codebook [4096,256] f32     (K=4096)
// output:  d_out[0..N*D) = embeddings (straight-through), d_out[N*D] = loss

#define NR    16384
#define KCB   4096
#define DDIM  256
#define BM    128
#define BN    128
#define BK    64
#define NCH   (DDIM / BK)        // 4 k-chunks
#define ROWB  144u               // padded smem row bytes (128 data + 16 pad)
#define ARRB  (128u * ROWB)      // 18432 B per array
#define STGB  (2u * ARRB)        // 36864 B per stage (Ah, Bh)
#define NSTG  2
#define SMEM_DYN (NSTG * STGB)   // 73728 B
#define EPS   0.15f
#define CAP   128                // candidate slots per row

// ---------------- scratch (__device__ globals) -------------------------------
__device__ __nv_bfloat16 g_Ahi[NR * DDIM];
__device__ __nv_bfloat16 g_Bhi[KCB * DDIM];
__device__ unsigned long long g_cand[(size_t)NR * CAP];  // (f32bits(dred)<<32)|col
__device__ int            g_cand_cnt[NR];
__device__ unsigned int   g_rowmin_approx[NR];       // enc(d_red) global per row
__device__ unsigned int   g_class_min[KCB];
__device__ int            g_active[KCB];
__device__ float          g_mse;
__device__ float          g_xsq[NR];
__device__ float          g_csq[KCB];

// ---------------- helpers ----------------------------------------------------
__device__ __forceinline__ unsigned int enc_f(float f) {
    unsigned int u = __float_as_uint(f);
    return (u & 0x80000000u) ? ~u : (u | 0x80000000u);
}
__device__ __forceinline__ float dec_f(unsigned int e) {
    return (e & 0x80000000u) ? __uint_as_float(e ^ 0x80000000u)
                             : __uint_as_float(~e);
}
__device__ __forceinline__ uint32_t smem_u32(const void* p) {
    uint32_t a;
    asm("{ .reg .u64 t; cvta.to.shared.u64 t, %1; cvt.u32.u64 %0, t; }"
        : "=r"(a) : "l"(p));
    return a;
}
__device__ __forceinline__ void cp16(uint32_t dst, const void* src) {
    asm volatile("cp.async.cg.shared.global [%0], [%1], 16;"
                 :: "r"(dst), "l"(src) : "memory");
}
#define CP_COMMIT() asm volatile("cp.async.commit_group;" ::: "memory")
#define CP_WAIT0()  asm volatile("cp.async.wait_group 0;" ::: "memory")

__device__ __forceinline__ void ldsm4(uint32_t r[4], uint32_t addr) {
    asm volatile("ldmatrix.sync.aligned.m8n8.x4.shared.b16 {%0,%1,%2,%3}, [%4];"
                 : "=r"(r[0]), "=r"(r[1]), "=r"(r[2]), "=r"(r[3]) : "r"(addr));
}
__device__ __forceinline__ void mma_bf16(float c[4], const uint32_t a[4],
                                         uint32_t b0, uint32_t b1) {
    asm volatile(
        "mma.sync.aligned.m16n8k16.row.col.f32.bf16.bf16.f32 "
        "{%0,%1,%2,%3}, {%4,%5,%6,%7}, {%8,%9}, {%0,%1,%2,%3};"
        : "+f"(c[0]), "+f"(c[1]), "+f"(c[2]), "+f"(c[3])
        : "r"(a[0]), "r"(a[1]), "r"(a[2]), "r"(a[3]), "r"(b0), "r"(b1));
}

// ---------------- init --------------------------------------------------------
__global__ void vq_init_kernel() {
    int i = blockIdx.x * blockDim.x + threadIdx.x;
    if (i < NR) { g_rowmin_approx[i] = 0xFFFFFFFFu; g_cand_cnt[i] = 0; }
    if (i < KCB) { g_class_min[i] = 0xFFFFFFFFu; g_active[i] = 0; }
    if (i == 0) g_mse = 0.0f;
}

// ---------------- bf16 convert + squared norms -------------------------------
__global__ void vq_split_kernel(const float* __restrict__ src, int rows, int which) {
    int warp = threadIdx.x >> 5;
    int lane = threadIdx.x & 31;
    int row  = blockIdx.x * 8 + warp;
    if (row >= rows) return;
    __nv_bfloat16* hi = which ? g_Bhi : g_Ahi;
    float*         sq = which ? g_csq : g_xsq;
    const float4* s4 = reinterpret_cast<const float4*>(src + (size_t)row * DDIM);
    __nv_bfloat162* h2 = reinterpret_cast<__nv_bfloat162*>(hi + (size_t)row * DDIM);
    float acc = 0.0f;
#pragma unroll
    for (int j = lane; j < DDIM / 4; j += 32) {
        float4 v = s4[j];
        h2[2 * j]     = __nv_bfloat162(__float2bfloat16_rn(v.x), __float2bfloat16_rn(v.y));
        h2[2 * j + 1] = __nv_bfloat162(__float2bfloat16_rn(v.z), __float2bfloat16_rn(v.w));
        acc += v.x * v.x + v.y * v.y + v.z * v.z + v.w * v.w;
    }
#pragma unroll
    for (int o = 16; o; o >>= 1) acc += __shfl_xor_sync(0xFFFFFFFFu, acc, o);
    if (lane == 0) sq[row] = acc;
}

// ---------------- fused GEMM (bf16 HMMA, BK=64, 2-stage, 2 CTA/SM) ------------
// CTA: 128x128, 512 threads = 16 warps in 4(M)x4(N); warp tile 32x32.
// Per chunk: WAIT0 -> sync -> LOAD(ch+1) -> compute(ch).
// Stage (ch+1)%2 was last read in chunk ch-1; sync(ch) proves all warps done.
// MMA k-order (ch x k16) identical to previous rounds -> bitwise-same results.
__global__ __launch_bounds__(512, 2)
void vq_gemm() {
    extern __shared__ char dynsm[];
    __shared__ unsigned int s_rowmin[BM];
    __shared__ unsigned int s_clsmin[BN];
    __shared__ float        s_xsq[BM];
    __shared__ float        s_csq[BN];

    const uint32_t sb = smem_u32(dynsm);
    const int tid  = threadIdx.x;
    const int lane = tid & 31;
    const int w    = tid >> 5;
    const int m_base = (w >> 2) * 32;
    const int n_base = (w & 3) * 32;
    const int tileM = blockIdx.y * BM;
    const int tileN = blockIdx.x * BN;

    if (tid < BM) {
        s_rowmin[tid] = 0xFFFFFFFFu;
        s_clsmin[tid] = 0xFFFFFFFFu;
        s_xsq[tid] = g_xsq[tileM + tid];
        s_csq[tid] = g_csq[tileN + tid];
    }

    const __nv_bfloat16* Ah = g_Ahi + (size_t)tileM * DDIM;
    const __nv_bfloat16* Bh = g_Bhi + (size_t)tileN * DDIM;

    float c[2][4][4];
#pragma unroll
    for (int mt = 0; mt < 2; mt++)
#pragma unroll
        for (int nt = 0; nt < 4; nt++)
#pragma unroll
            for (int r = 0; r < 4; r++) c[mt][nt][r] = 0.0f;

    // loader: per chunk 2 arrays x 128 rows x 8 chunks(16B); 512 thr ->
    //   per array 2 passes of (row = tid>>3 + 64p, c16 = tid&7); 4 cp16/thread.
    const int lrow = tid >> 3;          // 0..63
    const int lc16 = tid & 7;           // 0..7
    const uint32_t ldst = (uint32_t)lrow * ROWB + (uint32_t)lc16 * 16u;
    const size_t lsrc = (size_t)lrow * DDIM + lc16 * 8;

#define LOAD_CHUNK(stg, k0)                                              \
    do {                                                                 \
        uint32_t st_ = sb + (uint32_t)(stg) * STGB;                      \
        cp16(st_ + ldst,                      Ah + lsrc + (k0));         \
        cp16(st_ + 64u * ROWB + ldst,         Ah + 64 * DDIM + lsrc + (k0)); \
        cp16(st_ + ARRB + ldst,               Bh + lsrc + (k0));         \
        cp16(st_ + ARRB + 64u * ROWB + ldst,  Bh + 64 * DDIM + lsrc + (k0)); \
        CP_COMMIT();                                                     \
    } while (0)

    LOAD_CHUNK(0, 0);

    // ldmatrix lane addressing
    const uint32_t arow = (uint32_t)(m_base + (lane & 7) + 8 * ((lane >> 3) & 1));
    const uint32_t acol16 = 16u * (uint32_t)(lane >> 4);
    const uint32_t brow2 = (uint32_t)(n_base + ((lane >> 4) & 1) * 8 + (lane & 7));
    const uint32_t bcol2 = 16u * (uint32_t)((lane >> 3) & 1);

#pragma unroll
    for (int ch = 0; ch < NCH; ch++) {
        CP_WAIT0();          // chunk ch resident (only its group outstanding)
        __syncthreads();     // all warps done reading stage (ch+1)%2 (chunk ch-1)
        if (ch + 1 < NCH) LOAD_CHUNK((ch + 1) & 1, (ch + 1) * BK);

        const uint32_t st = sb + (uint32_t)(ch & 1) * STGB;
#pragma unroll
        for (int k16 = 0; k16 < 4; k16++) {       // 4 x 16-k slices per chunk
            uint32_t ah[2][4];
#pragma unroll
            for (int mt = 0; mt < 2; mt++) {
                uint32_t ra = (arow + 16u * mt) * ROWB + (uint32_t)(k16 * 32) + acol16;
                ldsm4(ah[mt], st + ra);
            }
            uint32_t bq[2][4];    // [pair p][m0..m3]; p=0 -> nt 0,1; p=1 -> nt 2,3
#pragma unroll
            for (int p = 0; p < 2; p++) {
                uint32_t rb = (brow2 + 16u * p) * ROWB + (uint32_t)(k16 * 32) + bcol2;
                ldsm4(bq[p], st + ARRB + rb);
            }
#pragma unroll
            for (int nt = 0; nt < 4; nt++) {
                uint32_t b0 = bq[nt >> 1][(nt & 1) * 2 + 0];
                uint32_t b1 = bq[nt >> 1][(nt & 1) * 2 + 1];
#pragma unroll
                for (int mt = 0; mt < 2; mt++)
                    mma_bf16(c[mt][nt], ah[mt], b0, b1);
            }
        }
    }

    // ---- epilogue: tile-local row-min + per-class min ----
    unsigned int cm[4][2];
#pragma unroll
    for (int nt = 0; nt < 4; nt++) { cm[nt][0] = 0xFFFFFFFFu; cm[nt][1] = 0xFFFFFFFFu; }

#pragma unroll
    for (int mt = 0; mt < 2; mt++)
#pragma unroll
        for (int h = 0; h < 2; h++) {
            const int rl = m_base + mt * 16 + (lane >> 2) + 8 * h;
            const float xq = s_xsq[rl];
            unsigned int best = 0xFFFFFFFFu;
#pragma unroll
            for (int nt = 0; nt < 4; nt++) {
                const int cl = n_base + nt * 8 + 2 * (lane & 3);
                float dr0 = fmaf(-2.0f, c[mt][nt][h * 2 + 0], s_csq[cl]);
                float dr1 = fmaf(-2.0f, c[mt][nt][h * 2 + 1], s_csq[cl + 1]);
                unsigned int e0 = enc_f(dr0);
                unsigned int e1 = enc_f(dr1);
                if (e0 < best) best = e0;
                if (e1 < best) best = e1;
                unsigned int f0 = enc_f(dr0 + xq);
                unsigned int f1 = enc_f(dr1 + xq);
                if (f0 < cm[nt][0]) cm[nt][0] = f0;
                if (f1 < cm[nt][1]) cm[nt][1] = f1;
            }
#pragma unroll
            for (int o = 1; o <= 2; o <<= 1) {
                unsigned int t = __shfl_xor_sync(0xFFFFFFFFu, best, o);
                if (t < best) best = t;
            }
            if ((lane & 3) == 0) atomicMin(&s_rowmin[rl], best);
        }

#pragma unroll
    for (int nt = 0; nt < 4; nt++)
#pragma unroll
        for (int b = 0; b < 2; b++) {
            unsigned int v = cm[nt][b];
#pragma unroll
            for (int o = 4; o <= 16; o <<= 1) {
                unsigned int t = __shfl_xor_sync(0xFFFFFFFFu, v, o);
                if (t < v) v = t;
            }
            if (lane < 4) atomicMin(&s_clsmin[n_base + nt * 8 + 2 * lane + b], v);
        }

    __syncthreads();
    if (tid < BM) {
        atomicMin(&g_rowmin_approx[tileM + tid], s_rowmin[tid]);
        atomicMin(&g_class_min[tileN + tid], s_clsmin[tid]);
    }

    // ---- candidate append: dred <= tile_min + EPS, quad-aggregated atomics ----
    // All __shfl_sync collectives execute unconditionally on every lane.
#pragma unroll
    for (int mt = 0; mt < 2; mt++)
#pragma unroll
        for (int h = 0; h < 2; h++) {
            const int rl = m_base + mt * 16 + (lane >> 2) + 8 * h;
            const int row = tileM + rl;
            const float thr = dec_f(s_rowmin[rl]) + EPS;
            unsigned int mask = 0;
#pragma unroll
            for (int nt = 0; nt < 4; nt++)
#pragma unroll
                for (int b = 0; b < 2; b++) {
                    const int cl = n_base + nt * 8 + 2 * (lane & 3) + b;
                    float dred = fmaf(-2.0f, c[mt][nt][h * 2 + b], s_csq[cl]);
                    if (dred <= thr) mask |= 1u << (nt * 2 + b);
                }
            int cnt = __popc(mask);
            int incl = cnt, t;
            t = __shfl_up_sync(0xFFFFFFFFu, incl, 1, 4); if ((lane & 3) >= 1) incl += t;
            t = __shfl_up_sync(0xFFFFFFFFu, incl, 2, 4); if ((lane & 3) >= 2) incl += t;
            int total = __shfl_sync(0xFFFFFFFFu, incl, 3, 4);
            int base = 0;
            if ((lane & 3) == 0 && total > 0)
                base = atomicAdd(&g_cand_cnt[row], total);
            base = __shfl_sync(0xFFFFFFFFu, base, 0, 4);   // unconditional
            int slot = base + (incl - cnt);
            if (mask) {
#pragma unroll
                for (int nt = 0; nt < 4; nt++)
#pragma unroll
                    for (int b = 0; b < 2; b++) {
                        if (mask & (1u << (nt * 2 + b))) {
                            const int cl = n_base + nt * 8 + 2 * (lane & 3) + b;
                            float dred = fmaf(-2.0f, c[mt][nt][h * 2 + b],
                                              s_csq[cl]);
                            if (slot < CAP)
                                g_cand[(size_t)row * CAP + slot] =
                                    ((unsigned long long)__float_as_uint(dred)
                                         << 32) |
                                    (unsigned int)(tileN + cl);
                            slot++;
                        }
                    }
            }
        }
}

// ---------------- fused refine + gather + MSE + active ------------------------
__global__ __launch_bounds__(256)
void vq_refine_gather(const float* __restrict__ xf, const float* __restrict__ cbf,
                      float* __restrict__ out) {
    const int warp = threadIdx.x >> 5;
    const int lane = threadIdx.x & 31;
    const int row  = blockIdx.x * 8 + warp;

    float s = 0.0f;
    if (row < NR) {
        const float thr = dec_f(g_rowmin_approx[row]) + EPS;
        const float4* xr = reinterpret_cast<const float4*>(xf + (size_t)row * DDIM);
        const float xq = g_xsq[row];
        const int cnt = g_cand_cnt[row];

        unsigned long long best = 0xFFFFFFFFFFFFFFFFull;
        if (cnt <= CAP) {
            const unsigned long long* cl = g_cand + (size_t)row * CAP;
            for (int i = lane; i < cnt; i += 32) {
                unsigned long long pc = cl[i];
                float dred = __uint_as_float((unsigned int)(pc >> 32));
                if (dred <= thr) {
                    const int col = (int)(pc & 0xFFFFFFFFull);
                    const float4* cr =
                        reinterpret_cast<const float4*>(cbf + (size_t)col * DDIM);
                    float dot = 0.0f;     // sequential k-order, one accumulator
#pragma unroll 8
                    for (int k = 0; k < DDIM / 4; k++) {
                        float4 a = xr[k];
                        float4 u = cr[k];
                        dot = fmaf(a.x, u.x, dot);
                        dot = fmaf(a.y, u.y, dot);
                        dot = fmaf(a.z, u.z, dot);
                        dot = fmaf(a.w, u.w, dot);
                    }
                    float dfull = fmaf(-2.0f, dot, xq + g_csq[col]);
                    unsigned long long p =
                        ((unsigned long long)enc_f(dfull) << 32) |
                        (unsigned int)col;
                    if (p < best) best = p;
                }
            }
        } else {
            // overflow fallback (deterministic): full exact scan of the row.
            for (int col = lane; col < KCB; col += 32) {
                const float4* cr =
                    reinterpret_cast<const float4*>(cbf + (size_t)col * DDIM);
                float dot = 0.0f;
#pragma unroll 8
                for (int k = 0; k < DDIM / 4; k++) {
                    float4 a = xr[k];
                    float4 u = cr[k];
                    dot = fmaf(a.x, u.x, dot);
                    dot = fmaf(a.y, u.y, dot);
                    dot = fmaf(a.z, u.z, dot);
                    dot = fmaf(a.w, u.w, dot);
                }
                float dfull = fmaf(-2.0f, dot, xq + g_csq[col]);
                unsigned long long p =
                    ((unsigned long long)enc_f(dfull) << 32) | (unsigned int)col;
                if (p < best) best = p;
            }
        }
#pragma unroll
        for (int o = 16; o; o >>= 1) {
            unsigned long long t = __shfl_xor_sync(0xFFFFFFFFu, best, o);
            if (t < best) best = t;
        }
        const unsigned int tok = (unsigned int)(best & 0xFFFFFFFFull);
        if (lane == 0) g_active[tok] = 1;

        const float4* cp = reinterpret_cast<const float4*>(cbf + (size_t)tok * DDIM);
        float4*       op = reinterpret_cast<float4*>(out + (size_t)row * DDIM);
#pragma unroll
        for (int j2 = lane; j2 < DDIM / 4; j2 += 32) {
            float4 cc = cp[j2];
            float4 v2 = xr[j2];
            op[j2] = cc;
            float dx = cc.x - v2.x, dy = cc.y - v2.y;
            float dz = cc.z - v2.z, dw = cc.w - v2.w;
            s += dx * dx + dy * dy + dz * dz + dw * dw;
        }
    }
#pragma unroll
    for (int o = 16; o; o >>= 1) s += __shfl_xor_sync(0xFFFFFFFFu, s, o);
    __shared__ float ws[8];
    if (lane == 0) ws[warp] = s;
    __syncthreads();
    if (threadIdx.x == 0) {
        float t = 0.0f;
#pragma unroll
        for (int w2 = 0; w2 < 8; w2++) t += ws[w2];
        atomicAdd(&g_mse, t);
    }
}

// ---------------- finalize loss ----------------------------------------------
__global__ void vq_finalize_kernel(float* __restrict__ out, int nd) {
    __shared__ float sh[256];
    float s = 0.0f;
    for (int k = threadIdx.x; k < KCB; k += 256) {
        if (g_active[k] == 0) s += dec_f(g_class_min[k]);
    }
    sh[threadIdx.x] = s;
    __syncthreads();
    for (int o = 128; o; o >>= 1) {
        if (threadIdx.x < o) sh[threadIdx.x] += sh[threadIdx.x + o];
        __syncthreads();
    }
    if (threadIdx.x == 0) {
        float mse = g_mse / (float)((size_t)NR * DDIM);
        float ent = sh[0] / (float)KCB;
        out[nd] = 1.25f * mse + 0.02f * ent;
    }
}

// ---------------- launcher ----------------------------------------------------
extern "C" void kernel_launch(void* const* d_in, const int* in_sizes, int n_in,
                              void* d_out, int out_size) {
    const float* x  = (const float*)d_in[0];
    const float* cb = (const float*)d_in[1];
    float* out = (float*)d_out;

    cudaFuncSetAttribute(vq_gemm,
                         cudaFuncAttributeMaxDynamicSharedMemorySize, SMEM_DYN);

    vq_init_kernel<<<(NR + 255) / 256, 256>>>();
    vq_split_kernel<<<NR / 8, 256>>>(x, NR, 0);
    vq_split_kernel<<<KCB / 8, 256>>>(cb, KCB, 1);

    dim3 grid(KCB / BN, NR / BM);   // (32, 128) = 4096 CTAs
    vq_gemm<<<grid, 512, SMEM_DYN>>>();

    vq_refine_gather<<<NR / 8, 256>>>(x, cb, out);
    vq_finalize_kernel<<<1, 256>>>(out, NR * DDIM);
}